// round 2
// baseline (speedup 1.0000x reference)
#include <cuda_runtime.h>

#define B_B 4096
#define N_TOK 49
#define DIM_ 256
#define HEADS_ 8
#define HEAD_DIM_ 32
#define NW_ 64
#define Q_SCALE 0.17677669529663687f   // 32^-0.5
#define M_ROWS (B_B * N_TOK)           // 200704

// ---------------- scratch (device globals: allowed) ----------------
__device__ __align__(16) float g_kvx[(size_t)M_ROWS * 512];
__device__ __align__(16) float g_kvy[(size_t)M_ROWS * 512];
__device__ __align__(16) float g_qx [(size_t)M_ROWS * 256];
__device__ __align__(16) float g_qy [(size_t)M_ROWS * 256];

// ---------------- GEMM: C[M,Ncol] = (A[M,256] @ W[256,Ncol] + bias) * scale ----
// Tiles: 64x64, K-tile 16, 256 threads, 4x4 micro-tile. M % 64 == 0, Ncol % 64 == 0.
__global__ __launch_bounds__(256) void gemm_k256(
    const float* __restrict__ A, const float* __restrict__ W,
    const float* __restrict__ bias, float* __restrict__ C,
    int Ncol, float scale)
{
    __shared__ float As[16][68];  // [k][m], padded (68*4=272B, 16B-aligned rows)
    __shared__ float Ws[16][68];  // [k][n], padded

    const int t  = threadIdx.x;
    const int tx = t & 15;
    const int ty = t >> 4;
    const int tileN = blockIdx.x * 64;
    const int tileM = blockIdx.y * 64;

    // A load mapping: row am (0..63), k-quad akq (0..3)
    const int am  = t >> 2;
    const int akq = t & 3;
    const float* Aptr = A + (size_t)(tileM + am) * 256 + (akq << 2);
    // W load mapping: k-row wr (0..15), col quad wc
    const int wr = t >> 4;
    const int wc = (t & 15) << 2;

    float acc[4][4];
#pragma unroll
    for (int i = 0; i < 4; i++)
#pragma unroll
        for (int j = 0; j < 4; j++) acc[i][j] = 0.f;

    for (int k0 = 0; k0 < 256; k0 += 16) {
        float4 a4 = *(const float4*)(Aptr + k0);
        float4 w4 = *(const float4*)(W + (size_t)(k0 + wr) * Ncol + tileN + wc);
        __syncthreads();
        As[akq * 4 + 0][am] = a4.x;
        As[akq * 4 + 1][am] = a4.y;
        As[akq * 4 + 2][am] = a4.z;
        As[akq * 4 + 3][am] = a4.w;
        *(float4*)&Ws[wr][wc] = w4;
        __syncthreads();
#pragma unroll
        for (int kk = 0; kk < 16; kk++) {
            float4 av = *(const float4*)&As[kk][ty * 4];
            float4 wv = *(const float4*)&Ws[kk][tx * 4];
            acc[0][0] += av.x * wv.x; acc[0][1] += av.x * wv.y;
            acc[0][2] += av.x * wv.z; acc[0][3] += av.x * wv.w;
            acc[1][0] += av.y * wv.x; acc[1][1] += av.y * wv.y;
            acc[1][2] += av.y * wv.z; acc[1][3] += av.y * wv.w;
            acc[2][0] += av.z * wv.x; acc[2][1] += av.z * wv.y;
            acc[2][2] += av.z * wv.z; acc[2][3] += av.z * wv.w;
            acc[3][0] += av.w * wv.x; acc[3][1] += av.w * wv.y;
            acc[3][2] += av.w * wv.z; acc[3][3] += av.w * wv.w;
        }
    }

    float4 bb = *(const float4*)&bias[tileN + tx * 4];
#pragma unroll
    for (int i = 0; i < 4; i++) {
        const int r = tileM + ty * 4 + i;
        float4 o;
        o.x = (acc[i][0] + bb.x) * scale;
        o.y = (acc[i][1] + bb.y) * scale;
        o.z = (acc[i][2] + bb.z) * scale;
        o.w = (acc[i][3] + bb.w) * scale;
        *(float4*)&C[(size_t)r * Ncol + tileN + tx * 4] = o;
    }
}

// ---------------- fused attention + output projection ----------------
// One CTA per window b. 256 threads.
// smem layout (floats), every segment padded to a multiple of 4 floats so
// float4 accesses stay 16B-aligned:
#define SM_QH   0                       // 49*33=1617 -> pad 1620
#define SM_KH   (SM_QH + 1620)
#define SM_VH   (SM_KH + 1620)
#define SM_P    (SM_VH + 1620)          // 49*50=2450 -> pad 2452
#define SM_BASE (SM_P + 2452)
#define SM_O    (SM_BASE + 2452)        // 9764 floats -> 39056 B, 16B-aligned
#define SM_RPT  (SM_O + 49 * 256)       // 169*8=1352 (mult of 4)
#define SM_RPI  (SM_RPT + 1352)         // 2401 -> pad 2404
#define SM_TOT  (SM_RPI + 2404)
#define ATTN_SMEM_BYTES (SM_TOT * 4)    // 104,256 B

__global__ __launch_bounds__(256) void attn_kernel(
    const float* __restrict__ Q,     // (B,49,256) pre-scaled
    const float* __restrict__ KV,    // (B,49,512): k=[0:256), v=[256:512)
    const float* __restrict__ nuc,   // (B,49)
    const float* __restrict__ mask,  // (64,49,49)
    const float* __restrict__ rpbt,  // (169,8)
    const int*   __restrict__ rpi,   // (49,49)
    const float* __restrict__ Wp,    // (256,256)
    const float* __restrict__ bp,    // (256,)
    float* __restrict__ Out)         // (B,49,256)
{
    extern __shared__ float sm[];
    float* qh   = sm + SM_QH;
    float* kh   = sm + SM_KH;
    float* vh   = sm + SM_VH;
    float* P    = sm + SM_P;
    float* base = sm + SM_BASE;
    float* Osh  = sm + SM_O;
    float* rpt  = sm + SM_RPT;
    int*   rps  = (int*)(sm + SM_RPI);

    const int b = blockIdx.x;
    const int t = threadIdx.x;
    const int wi = b & (NW_ - 1);        // b % 64
    const float* nb = nuc + (size_t)b * 49;

    for (int idx = t; idx < 2401; idx += 256) rps[idx] = rpi[idx];
    for (int idx = t; idx < 1352; idx += 256) rpt[idx] = rpbt[idx];
    for (int idx = t; idx < 2401; idx += 256) {
        int i = idx / 49, j = idx % 49;
        base[i * 50 + j] = nb[i] + nb[j] + mask[((size_t)wi * 49 + i) * 49 + j];
    }
    __syncthreads();

    const int warp = t >> 5, lane = t & 31;

    for (int h = 0; h < HEADS_; h++) {
        const float* Qb = Q  + (size_t)b * 49 * 256 + h * 32;
        const float* Kb = KV + (size_t)b * 49 * 512 + h * 32;
        const float* Vb = KV + (size_t)b * 49 * 512 + 256 + h * 32;
        for (int idx = t; idx < 49 * 32; idx += 256) {
            int i = idx >> 5, d = idx & 31;
            qh[i * 33 + d] = Qb[(size_t)i * 256 + d];
            kh[i * 33 + d] = Kb[(size_t)i * 512 + d];
            vh[i * 33 + d] = Vb[(size_t)i * 512 + d];
        }
        __syncthreads();

        // logits
        for (int idx = t; idx < 2401; idx += 256) {
            int i = idx / 49, j = idx % 49;
            const float* qr = qh + i * 33;
            const float* kr = kh + j * 33;
            float s = 0.f;
#pragma unroll
            for (int d = 0; d < 32; d++) s += qr[d] * kr[d];
            P[i * 50 + j] = s + base[i * 50 + j] + rpt[rps[idx] * 8 + h];
        }
        __syncthreads();

        // softmax: one warp per row, lane covers j and j+32
        for (int i = warp; i < 49; i += 8) {
            float v0 = (lane < 49)      ? P[i * 50 + lane]      : -1e30f;
            float v1 = (lane + 32 < 49) ? P[i * 50 + lane + 32] : -1e30f;
            float m = fmaxf(v0, v1);
#pragma unroll
            for (int o = 16; o; o >>= 1) m = fmaxf(m, __shfl_xor_sync(0xffffffffu, m, o));
            float e0 = (lane < 49)      ? __expf(v0 - m) : 0.f;
            float e1 = (lane + 32 < 49) ? __expf(v1 - m) : 0.f;
            float ssum = e0 + e1;
#pragma unroll
            for (int o = 16; o; o >>= 1) ssum += __shfl_xor_sync(0xffffffffu, ssum, o);
            float inv = 1.f / ssum;
            if (lane < 49)      P[i * 50 + lane]      = e0 * inv;
            if (lane + 32 < 49) P[i * 50 + lane + 32] = e1 * inv;
        }
        __syncthreads();

        // O_h = P @ V_h   (49x49 @ 49x32)
        for (int idx = t; idx < 49 * 32; idx += 256) {
            int i = idx >> 5, d = idx & 31;
            const float* pr = P + i * 50;
            float a = 0.f;
#pragma unroll
            for (int j = 0; j < 49; j++) a += pr[j] * vh[j * 33 + d];
            Osh[i * 256 + h * 32 + d] = a;
        }
        __syncthreads();
    }

    // output projection: out[i][t] = sum_d Osh[i][d] * Wp[d][t] + bp[t]
    float accp[49];
#pragma unroll
    for (int i = 0; i < 49; i++) accp[i] = 0.f;

    for (int d = 0; d < 256; d += 4) {
        float w0 = Wp[(size_t)(d + 0) * 256 + t];
        float w1 = Wp[(size_t)(d + 1) * 256 + t];
        float w2 = Wp[(size_t)(d + 2) * 256 + t];
        float w3 = Wp[(size_t)(d + 3) * 256 + t];
#pragma unroll
        for (int i = 0; i < 49; i++) {
            float4 o4 = *(const float4*)&Osh[i * 256 + d];
            accp[i] += o4.x * w0 + o4.y * w1 + o4.z * w2 + o4.w * w3;
        }
    }
    float bv = bp[t];
    float* ob = Out + (size_t)b * 49 * 256 + t;
#pragma unroll
    for (int i = 0; i < 49; i++) ob[(size_t)i * 256] = accp[i] + bv;
}

// ---------------- nuclei passthrough ----------------
__global__ void copy_nuc(const float* __restrict__ in, float* __restrict__ out, int n)
{
    int i = blockIdx.x * 256 + threadIdx.x;
    if (i < n) out[i] = in[i];
}

// ---------------- launch ----------------
extern "C" void kernel_launch(void* const* d_in, const int* in_sizes, int n_in,
                              void* d_out, int out_size)
{
    const float* x        = (const float*)d_in[0];
    const float* y        = (const float*)d_in[1];
    const float* nuc      = (const float*)d_in[2];
    const float* mask     = (const float*)d_in[3];
    const float* rpbt     = (const float*)d_in[4];
    const float* qkv_w    = (const float*)d_in[5];
    const float* qkv_b    = (const float*)d_in[6];
    const float* qkv_y_w  = (const float*)d_in[7];
    const float* qkv_y_b  = (const float*)d_in[8];
    const float* proj_qx_w= (const float*)d_in[9];
    const float* proj_qx_b= (const float*)d_in[10];
    const float* proj_qy_w= (const float*)d_in[11];
    const float* proj_qy_b= (const float*)d_in[12];
    const float* proj_w   = (const float*)d_in[13];
    const float* proj_b   = (const float*)d_in[14];
    const float* proj_y_w = (const float*)d_in[15];
    const float* proj_y_b = (const float*)d_in[16];
    const int*   rpi      = (const int*)d_in[17];
    float* out = (float*)d_out;

    float *kvx, *kvy, *qx, *qy;
    cudaGetSymbolAddress((void**)&kvx, g_kvx);
    cudaGetSymbolAddress((void**)&kvy, g_kvy);
    cudaGetSymbolAddress((void**)&qx,  g_qx);
    cudaGetSymbolAddress((void**)&qy,  g_qy);

    cudaFuncSetAttribute(attn_kernel, cudaFuncAttributeMaxDynamicSharedMemorySize,
                         ATTN_SMEM_BYTES);

    const int mtiles = M_ROWS / 64;  // 3136

    // projections
    gemm_k256<<<dim3(512 / 64, mtiles), 256>>>(x, qkv_w,     qkv_b,     kvx, 512, 1.f);
    gemm_k256<<<dim3(512 / 64, mtiles), 256>>>(y, qkv_y_w,   qkv_y_b,   kvy, 512, 1.f);
    gemm_k256<<<dim3(256 / 64, mtiles), 256>>>(x, proj_qx_w, proj_qx_b, qx,  256, Q_SCALE);
    gemm_k256<<<dim3(256 / 64, mtiles), 256>>>(y, proj_qy_w, proj_qy_b, qy,  256, Q_SCALE);

    // path 0: x_out = softmax(q_y k_x^T + bias) v_x @ proj_w
    attn_kernel<<<B_B, 256, ATTN_SMEM_BYTES>>>(qy, kvx, nuc, mask, rpbt, rpi,
                                               proj_w, proj_b, out);
    // path 1: y_out = softmax(q_x k_y^T + bias) v_y @ proj_y_w
    attn_kernel<<<B_B, 256, ATTN_SMEM_BYTES>>>(qx, kvy, nuc, mask, rpbt, rpi,
                                               proj_y_w, proj_y_b,
                                               out + (size_t)M_ROWS * 256);

    // nuclei passthrough
    copy_nuc<<<(M_ROWS + 255) / 256, 256>>>(nuc, out + 2 * (size_t)M_ROWS * 256,
                                            M_ROWS);
}

// round 3
// speedup vs baseline: 1.7051x; 1.7051x over previous
#include <cuda_runtime.h>

#define B_B 4096
#define N_TOK 49
#define DIM_ 256
#define HEADS_ 8
#define NW_ 64
#define Q_SCALE 0.17677669529663687f   // 32^-0.5
#define M_ROWS (B_B * N_TOK)           // 200704

// ---------------- scratch (device globals) ----------------
__device__ __align__(16) float g_xbuf[(size_t)M_ROWS * 768]; // k|v|q per row
__device__ __align__(16) float g_ybuf[(size_t)M_ROWS * 768];
__device__ __align__(16) float g_ox  [(size_t)M_ROWS * 256];
__device__ __align__(16) float g_oy  [(size_t)M_ROWS * 256];
__device__ __align__(16) float g_wx  [256 * 768];
__device__ __align__(16) float g_wy  [256 * 768];
__device__ __align__(16) float g_bx  [768];
__device__ __align__(16) float g_by  [768];

// ---------------- helpers ----------------
__device__ __forceinline__ unsigned f2tf(float f) {
    unsigned u;
    asm("cvt.rna.tf32.f32 %0, %1;" : "=r"(u) : "f"(f));
    return u;
}
__device__ __forceinline__ void mma_tf32(float* c, const unsigned* a, const unsigned* b) {
    asm volatile(
        "mma.sync.aligned.m16n8k8.row.col.f32.tf32.tf32.f32 "
        "{%0,%1,%2,%3}, {%4,%5,%6,%7}, {%8,%9}, {%0,%1,%2,%3};\n"
        : "+f"(c[0]), "+f"(c[1]), "+f"(c[2]), "+f"(c[3])
        : "r"(a[0]), "r"(a[1]), "r"(a[2]), "r"(a[3]), "r"(b[0]), "r"(b[1]));
}

// ---------------- weight concat: Wc[256,768] = [qkv_w | q_w*SCALE] ----------
__global__ void prep_w(const float* __restrict__ qkv_w, const float* __restrict__ qkv_b,
                       const float* __restrict__ qw, const float* __restrict__ qb,
                       float* __restrict__ Wc, float* __restrict__ bc)
{
    int i = blockIdx.x * 256 + threadIdx.x;
    if (i < 256 * 768) {
        int r = i / 768, ccol = i % 768;
        Wc[i] = (ccol < 512) ? qkv_w[r * 512 + ccol]
                             : qw[r * 256 + (ccol - 512)] * Q_SCALE;
    }
    if (i < 768) bc[i] = (i < 512) ? qkv_b[i] : qb[i - 512] * Q_SCALE;
}

// ---------------- tf32 tensor-core GEMM ----------------
// C[M,Ncol] = A[M,256] @ W[256,Ncol] + bias.  lda = 256 (fixed), ldw = ldc = Ncol.
// CTA tile 128x64, 256 threads = 8 warps (4 m x 2 n), warp tile 32x32.
// K-step 16. mma.m16n8k8 tf32.
__global__ __launch_bounds__(256) void gemm_tf32(
    const float* __restrict__ A, const float* __restrict__ W,
    const float* __restrict__ bias, float* __restrict__ C, int Ncol)
{
    __shared__ unsigned As[128][20];  // [m][k], pad 20 -> conflict-free frag loads
    __shared__ unsigned Bs[16][72];   // [k][n], pad 72 -> conflict-free frag loads

    const int t = threadIdx.x;
    const int warpId = t >> 5, lane = t & 31;
    const int gid = lane >> 2;        // 0..7
    const int tid4 = lane & 3;        // 0..3
    const int wm = (warpId & 3) * 32;
    const int wn = (warpId >> 2) * 32;
    const int tileM = blockIdx.y * 128;
    const int tileN = blockIdx.x * 64;

    // A gmem mapping: row = t>>1 (0..127), k-half = (t&1)*8
    const int arow = t >> 1;
    const int akq = (t & 1) * 8;
    const float* Ap = A + (size_t)(tileM + arow) * 256 + akq;
    // B gmem mapping: krow = t>>4 (0..15), ncol quad = (t&15)*4
    const int bkr = t >> 4;
    const int bnc = (t & 15) * 4;
    const float* Wp = W + (size_t)bkr * Ncol + tileN + bnc;

    float c[8][4];
#pragma unroll
    for (int i = 0; i < 8; i++)
#pragma unroll
        for (int j = 0; j < 4; j++) c[i][j] = 0.f;

    float4 pa0 = *(const float4*)(Ap);
    float4 pa1 = *(const float4*)(Ap + 4);
    float4 pb  = *(const float4*)(Wp);

    for (int k0 = 0; k0 < 256; k0 += 16) {
        // commit prefetched tile to smem (as tf32 bits)
        {
            uint4 ua0 = { f2tf(pa0.x), f2tf(pa0.y), f2tf(pa0.z), f2tf(pa0.w) };
            uint4 ua1 = { f2tf(pa1.x), f2tf(pa1.y), f2tf(pa1.z), f2tf(pa1.w) };
            uint4 ub  = { f2tf(pb.x),  f2tf(pb.y),  f2tf(pb.z),  f2tf(pb.w)  };
            *(uint4*)&As[arow][akq]     = ua0;
            *(uint4*)&As[arow][akq + 4] = ua1;
            *(uint4*)&Bs[bkr][bnc]      = ub;
        }
        __syncthreads();

        // prefetch next K tile
        if (k0 + 16 < 256) {
            pa0 = *(const float4*)(Ap + k0 + 16);
            pa1 = *(const float4*)(Ap + k0 + 20);
            pb  = *(const float4*)(Wp + (size_t)(k0 + 16) * Ncol);
        }

        // compute: 2 k8 sub-steps
#pragma unroll
        for (int kh = 0; kh < 16; kh += 8) {
            unsigned a[2][4], b[4][2];
#pragma unroll
            for (int mt = 0; mt < 2; mt++) {
                int r = wm + mt * 16 + gid;
                a[mt][0] = As[r][kh + tid4];
                a[mt][1] = As[r + 8][kh + tid4];
                a[mt][2] = As[r][kh + tid4 + 4];
                a[mt][3] = As[r + 8][kh + tid4 + 4];
            }
#pragma unroll
            for (int nt = 0; nt < 4; nt++) {
                int ncol = wn + nt * 8 + gid;
                b[nt][0] = Bs[kh + tid4][ncol];
                b[nt][1] = Bs[kh + tid4 + 4][ncol];
            }
#pragma unroll
            for (int mt = 0; mt < 2; mt++)
#pragma unroll
                for (int nt = 0; nt < 4; nt++)
                    mma_tf32(c[mt * 4 + nt], a[mt], b[nt]);
        }
        __syncthreads();
    }

    // epilogue
#pragma unroll
    for (int mt = 0; mt < 2; mt++) {
        int row = tileM + wm + mt * 16 + gid;
#pragma unroll
        for (int nt = 0; nt < 4; nt++) {
            int col = tileN + wn + nt * 8 + tid4 * 2;
            float bx = bias[col], by = bias[col + 1];
            float2 v0 = { c[mt * 4 + nt][0] + bx, c[mt * 4 + nt][1] + by };
            float2 v1 = { c[mt * 4 + nt][2] + bx, c[mt * 4 + nt][3] + by };
            *(float2*)&C[(size_t)row * Ncol + col] = v0;
            *(float2*)&C[(size_t)(row + 8) * Ncol + col] = v1;
        }
    }
}

// ---------------- attention core (no projection) ----------------
// One CTA per window b. 256 threads. Row stride of Q/KV buffers = 768.
#define SM_QH   0                       // 49*33=1617 -> pad 1620
#define SM_KH   (SM_QH + 1620)
#define SM_VH   (SM_KH + 1620)
#define SM_P    (SM_VH + 1620)          // 49*50=2450 -> pad 2452
#define SM_BASE (SM_P + 2452)
#define SM_RPT  (SM_BASE + 2452)        // 1352
#define SM_RPI  (SM_RPT + 1352)         // 2401 -> pad 2404
#define SM_TOT  (SM_RPI + 2404)
#define ATTN_SMEM_BYTES (SM_TOT * 4)

__global__ __launch_bounds__(256) void attn_kernel(
    const float* __restrict__ Q,     // base + 512 offset, row stride 768 (pre-scaled)
    const float* __restrict__ KV,    // row stride 768: k=[0:256), v=[256:512)
    const float* __restrict__ nuc,   // (B,49)
    const float* __restrict__ mask,  // (64,49,49)
    const float* __restrict__ rpbt,  // (169,8)
    const int*   __restrict__ rpi,   // (49,49)
    float* __restrict__ gO)          // (B,49,256)
{
    extern __shared__ float sm[];
    float* qh   = sm + SM_QH;
    float* kh   = sm + SM_KH;
    float* vh   = sm + SM_VH;
    float* P    = sm + SM_P;
    float* base = sm + SM_BASE;
    float* rpt  = sm + SM_RPT;
    int*   rps  = (int*)(sm + SM_RPI);

    const int b = blockIdx.x;
    const int t = threadIdx.x;
    const int wi = b & (NW_ - 1);
    const float* nb = nuc + (size_t)b * 49;

    for (int idx = t; idx < 2401; idx += 256) rps[idx] = rpi[idx];
    for (int idx = t; idx < 1352; idx += 256) rpt[idx] = rpbt[idx];
    for (int idx = t; idx < 2401; idx += 256) {
        int i = idx / 49, j = idx % 49;
        base[i * 50 + j] = nb[i] + nb[j] + mask[((size_t)wi * 49 + i) * 49 + j];
    }
    __syncthreads();

    const int warp = t >> 5, lane = t & 31;

    for (int h = 0; h < HEADS_; h++) {
        const float* Qb = Q  + (size_t)b * 49 * 768 + h * 32;
        const float* Kb = KV + (size_t)b * 49 * 768 + h * 32;
        const float* Vb = KV + (size_t)b * 49 * 768 + 256 + h * 32;
        for (int idx = t; idx < 49 * 32; idx += 256) {
            int i = idx >> 5, d = idx & 31;
            qh[i * 33 + d] = Qb[(size_t)i * 768 + d];
            kh[i * 33 + d] = Kb[(size_t)i * 768 + d];
            vh[i * 33 + d] = Vb[(size_t)i * 768 + d];
        }
        __syncthreads();

        // logits
        for (int idx = t; idx < 2401; idx += 256) {
            int i = idx / 49, j = idx % 49;
            const float* qr = qh + i * 33;
            const float* kr = kh + j * 33;
            float s = 0.f;
#pragma unroll
            for (int d = 0; d < 32; d++) s += qr[d] * kr[d];
            P[i * 50 + j] = s + base[i * 50 + j] + rpt[rps[idx] * 8 + h];
        }
        __syncthreads();

        // softmax: one warp per row
        for (int i = warp; i < 49; i += 8) {
            float v0 = (lane < 49)      ? P[i * 50 + lane]      : -1e30f;
            float v1 = (lane + 32 < 49) ? P[i * 50 + lane + 32] : -1e30f;
            float m = fmaxf(v0, v1);
#pragma unroll
            for (int o = 16; o; o >>= 1) m = fmaxf(m, __shfl_xor_sync(0xffffffffu, m, o));
            float e0 = (lane < 49)      ? __expf(v0 - m) : 0.f;
            float e1 = (lane + 32 < 49) ? __expf(v1 - m) : 0.f;
            float ssum = e0 + e1;
#pragma unroll
            for (int o = 16; o; o >>= 1) ssum += __shfl_xor_sync(0xffffffffu, ssum, o);
            float inv = 1.f / ssum;
            if (lane < 49)      P[i * 50 + lane]      = e0 * inv;
            if (lane + 32 < 49) P[i * 50 + lane + 32] = e1 * inv;
        }
        __syncthreads();

        // O_h = P @ V_h, write straight to global scratch
        for (int idx = t; idx < 49 * 32; idx += 256) {
            int i = idx >> 5, d = idx & 31;
            const float* pr = P + i * 50;
            float a = 0.f;
#pragma unroll
            for (int j = 0; j < 49; j++) a += pr[j] * vh[j * 33 + d];
            gO[(size_t)b * 49 * 256 + i * 256 + h * 32 + d] = a;
        }
        __syncthreads();
    }
}

// ---------------- nuclei passthrough ----------------
__global__ void copy_nuc(const float* __restrict__ in, float* __restrict__ out, int n)
{
    int i = blockIdx.x * 256 + threadIdx.x;
    if (i < n) out[i] = in[i];
}

// ---------------- launch ----------------
extern "C" void kernel_launch(void* const* d_in, const int* in_sizes, int n_in,
                              void* d_out, int out_size)
{
    const float* x        = (const float*)d_in[0];
    const float* y        = (const float*)d_in[1];
    const float* nuc      = (const float*)d_in[2];
    const float* mask     = (const float*)d_in[3];
    const float* rpbt     = (const float*)d_in[4];
    const float* qkv_w    = (const float*)d_in[5];
    const float* qkv_b    = (const float*)d_in[6];
    const float* qkv_y_w  = (const float*)d_in[7];
    const float* qkv_y_b  = (const float*)d_in[8];
    const float* proj_qx_w= (const float*)d_in[9];
    const float* proj_qx_b= (const float*)d_in[10];
    const float* proj_qy_w= (const float*)d_in[11];
    const float* proj_qy_b= (const float*)d_in[12];
    const float* proj_w   = (const float*)d_in[13];
    const float* proj_b   = (const float*)d_in[14];
    const float* proj_y_w = (const float*)d_in[15];
    const float* proj_y_b = (const float*)d_in[16];
    const int*   rpi      = (const int*)d_in[17];
    float* out = (float*)d_out;

    float *xbuf, *ybuf, *ox, *oy, *wx, *wy, *bx, *by;
    cudaGetSymbolAddress((void**)&xbuf, g_xbuf);
    cudaGetSymbolAddress((void**)&ybuf, g_ybuf);
    cudaGetSymbolAddress((void**)&ox,   g_ox);
    cudaGetSymbolAddress((void**)&oy,   g_oy);
    cudaGetSymbolAddress((void**)&wx,   g_wx);
    cudaGetSymbolAddress((void**)&wy,   g_wy);
    cudaGetSymbolAddress((void**)&bx,   g_bx);
    cudaGetSymbolAddress((void**)&by,   g_by);

    cudaFuncSetAttribute(attn_kernel, cudaFuncAttributeMaxDynamicSharedMemorySize,
                         ATTN_SMEM_BYTES);

    // weight concat (tiny)
    prep_w<<<768, 256>>>(qkv_w,   qkv_b,   proj_qx_w, proj_qx_b, wx, bx);
    prep_w<<<768, 256>>>(qkv_y_w, qkv_y_b, proj_qy_w, proj_qy_b, wy, by);

    const int mtiles = M_ROWS / 128;  // 1568

    // fused input projections: [k|v|q] per row
    gemm_tf32<<<dim3(768 / 64, mtiles), 256>>>(x, wx, bx, xbuf, 768);
    gemm_tf32<<<dim3(768 / 64, mtiles), 256>>>(y, wy, by, ybuf, 768);

    // attention cores
    // path 0 (x_out): q from y, k/v from x
    attn_kernel<<<B_B, 256, ATTN_SMEM_BYTES>>>(ybuf + 512, xbuf, nuc, mask, rpbt, rpi, ox);
    // path 1 (y_out): q from x, k/v from y
    attn_kernel<<<B_B, 256, ATTN_SMEM_BYTES>>>(xbuf + 512, ybuf, nuc, mask, rpbt, rpi, oy);

    // output projections
    gemm_tf32<<<dim3(256 / 64, mtiles), 256>>>(ox, proj_w,   proj_b,   out, 256);
    gemm_tf32<<<dim3(256 / 64, mtiles), 256>>>(oy, proj_y_w, proj_y_b,
                                               out + (size_t)M_ROWS * 256, 256);

    // nuclei passthrough
    copy_nuc<<<(M_ROWS + 255) / 256, 256>>>(nuc, out + 2 * (size_t)M_ROWS * 256, M_ROWS);
}

// round 4
// speedup vs baseline: 2.1052x; 1.2347x over previous
#include <cuda_runtime.h>

#define B_B 4096
#define N_TOK 49
#define DIM_ 256
#define HEADS_ 8
#define NW_ 64
#define Q_SCALE 0.17677669529663687f   // 32^-0.5
#define M_ROWS (B_B * N_TOK)           // 200704

// ---------------- scratch (device globals) ----------------
__device__ __align__(16) float g_xbuf[(size_t)M_ROWS * 768]; // k|v|q per row
__device__ __align__(16) float g_ybuf[(size_t)M_ROWS * 768];
__device__ __align__(16) float g_ox  [(size_t)M_ROWS * 256];
__device__ __align__(16) float g_oy  [(size_t)M_ROWS * 256];
__device__ __align__(16) float g_wx  [256 * 768];
__device__ __align__(16) float g_wy  [256 * 768];
__device__ __align__(16) float g_bx  [768];
__device__ __align__(16) float g_by  [768];

// ---------------- helpers ----------------
__device__ __forceinline__ unsigned f2tf(float f) {
    unsigned u;
    asm("cvt.rna.tf32.f32 %0, %1;" : "=r"(u) : "f"(f));
    return u;
}
__device__ __forceinline__ void mma_tf32(float* c, const unsigned* a, const unsigned* b) {
    asm volatile(
        "mma.sync.aligned.m16n8k8.row.col.f32.tf32.tf32.f32 "
        "{%0,%1,%2,%3}, {%4,%5,%6,%7}, {%8,%9}, {%0,%1,%2,%3};\n"
        : "+f"(c[0]), "+f"(c[1]), "+f"(c[2]), "+f"(c[3])
        : "r"(a[0]), "r"(a[1]), "r"(a[2]), "r"(a[3]), "r"(b[0]), "r"(b[1]));
}

// ---------------- weight concat: Wc[256,768] = [qkv_w | q_w*SCALE] ----------
__global__ void prep_w(const float* __restrict__ qkv_w, const float* __restrict__ qkv_b,
                       const float* __restrict__ qw, const float* __restrict__ qb,
                       float* __restrict__ Wc, float* __restrict__ bc)
{
    int i = blockIdx.x * 256 + threadIdx.x;
    if (i < 256 * 768) {
        int r = i / 768, ccol = i % 768;
        Wc[i] = (ccol < 512) ? qkv_w[r * 512 + ccol]
                             : qw[r * 256 + (ccol - 512)] * Q_SCALE;
    }
    if (i < 768) bc[i] = (i < 512) ? qkv_b[i] : qb[i - 512] * Q_SCALE;
}

// ---------------- tf32 tensor-core GEMM ----------------
// C[M,Ncol] = A[M,256] @ W[256,Ncol] + bias.  lda = 256 (fixed), ldw = ldc = Ncol.
// CTA tile 128x128, 256 threads = 8 warps (2 m x 4 n), warp tile 64x32.
__global__ __launch_bounds__(256, 2) void gemm_tf32(
    const float* __restrict__ A, const float* __restrict__ W,
    const float* __restrict__ bias, float* __restrict__ C, int Ncol)
{
    __shared__ unsigned As[128][20];   // [m][k], pad 20 -> conflict-free frag loads
    __shared__ unsigned Bs[16][136];   // [k][n], pad 136 -> conflict-free frag loads

    const int t = threadIdx.x;
    const int warpId = t >> 5, lane = t & 31;
    const int gid = lane >> 2;
    const int tid4 = lane & 3;
    const int wm = (warpId & 1) * 64;
    const int wn = (warpId >> 1) * 32;
    const int tileM = blockIdx.y * 128;
    const int tileN = blockIdx.x * 128;

    // A gmem mapping: row = t>>1 (0..127), k-half = (t&1)*8
    const int arow = t >> 1;
    const int akq = (t & 1) * 8;
    const float* Ap = A + (size_t)(tileM + arow) * 256 + akq;
    // B gmem mapping: krow = t>>4 (0..15), cols (t&15)*4 and +64
    const int bkr = t >> 4;
    const int bnc = (t & 15) * 4;
    const float* Wp = W + (size_t)bkr * Ncol + tileN + bnc;

    float c[16][4];
#pragma unroll
    for (int i = 0; i < 16; i++)
#pragma unroll
        for (int j = 0; j < 4; j++) c[i][j] = 0.f;

    float4 pa0 = *(const float4*)(Ap);
    float4 pa1 = *(const float4*)(Ap + 4);
    float4 pb0 = *(const float4*)(Wp);
    float4 pb1 = *(const float4*)(Wp + 64);

    for (int k0 = 0; k0 < 256; k0 += 16) {
        {
            uint4 ua0 = { f2tf(pa0.x), f2tf(pa0.y), f2tf(pa0.z), f2tf(pa0.w) };
            uint4 ua1 = { f2tf(pa1.x), f2tf(pa1.y), f2tf(pa1.z), f2tf(pa1.w) };
            uint4 ub0 = { f2tf(pb0.x), f2tf(pb0.y), f2tf(pb0.z), f2tf(pb0.w) };
            uint4 ub1 = { f2tf(pb1.x), f2tf(pb1.y), f2tf(pb1.z), f2tf(pb1.w) };
            *(uint4*)&As[arow][akq]      = ua0;
            *(uint4*)&As[arow][akq + 4]  = ua1;
            *(uint4*)&Bs[bkr][bnc]       = ub0;
            *(uint4*)&Bs[bkr][bnc + 64]  = ub1;
        }
        __syncthreads();

        if (k0 + 16 < 256) {
            pa0 = *(const float4*)(Ap + k0 + 16);
            pa1 = *(const float4*)(Ap + k0 + 20);
            pb0 = *(const float4*)(Wp + (size_t)(k0 + 16) * Ncol);
            pb1 = *(const float4*)(Wp + (size_t)(k0 + 16) * Ncol + 64);
        }

#pragma unroll
        for (int kh = 0; kh < 16; kh += 8) {
            unsigned a[4][4], b[4][2];
#pragma unroll
            for (int mt = 0; mt < 4; mt++) {
                int r = wm + mt * 16 + gid;
                a[mt][0] = As[r][kh + tid4];
                a[mt][1] = As[r + 8][kh + tid4];
                a[mt][2] = As[r][kh + tid4 + 4];
                a[mt][3] = As[r + 8][kh + tid4 + 4];
            }
#pragma unroll
            for (int nt = 0; nt < 4; nt++) {
                int ncol = wn + nt * 8 + gid;
                b[nt][0] = Bs[kh + tid4][ncol];
                b[nt][1] = Bs[kh + tid4 + 4][ncol];
            }
#pragma unroll
            for (int mt = 0; mt < 4; mt++)
#pragma unroll
                for (int nt = 0; nt < 4; nt++)
                    mma_tf32(c[mt * 4 + nt], a[mt], b[nt]);
        }
        __syncthreads();
    }

    // epilogue
#pragma unroll
    for (int mt = 0; mt < 4; mt++) {
        int row = tileM + wm + mt * 16 + gid;
#pragma unroll
        for (int nt = 0; nt < 4; nt++) {
            int col = tileN + wn + nt * 8 + tid4 * 2;
            float bx = bias[col], by = bias[col + 1];
            float2 v0 = { c[mt * 4 + nt][0] + bx, c[mt * 4 + nt][1] + by };
            float2 v1 = { c[mt * 4 + nt][2] + bx, c[mt * 4 + nt][3] + by };
            *(float2*)&C[(size_t)row * Ncol + col] = v0;
            *(float2*)&C[(size_t)(row + 8) * Ncol + col] = v1;
        }
    }
}

// ---------------- tensor-core attention core ----------------
// One CTA per window b, 256 threads = 8 warps. 49 padded to 64.
// smem segments (4B units), all multiples of 4:
#define SA_QT   0                        // 64*33 u32 = 2112
#define SA_KT   (SA_QT + 2112)
#define SA_VT   (SA_KT + 2112)
#define SA_PSM  (SA_VT + 2112)           // 64*66 u32 = 4224
#define SA_BIAS (SA_PSM + 4224)          // 64*65 f32 = 4160
#define SA_BASE (SA_BIAS + 4160)         // 49*50 -> 2452
#define SA_RPT  (SA_BASE + 2452)         // 1352
#define SA_RPI  (SA_RPT + 1352)          // 2401 -> 2404
#define SA_RED  (SA_RPI + 2404)          // 128
#define SA_RED2 (SA_RED + 128)           // 128
#define SA_TOT  (SA_RED2 + 128)
#define ATTN_SMEM_BYTES (SA_TOT * 4)     // 84,736 B

__global__ __launch_bounds__(256) void attn_kernel(
    const float* __restrict__ Q,     // q section, row stride 768 (pre-scaled)
    const float* __restrict__ KV,    // row stride 768: k=[0:256), v=[256:512)
    const float* __restrict__ nuc,   // (B,49)
    const float* __restrict__ mask,  // (64,49,49)
    const float* __restrict__ rpbt,  // (169,8)
    const int*   __restrict__ rpi,   // (49,49)
    float* __restrict__ gO)          // (B,49,256)
{
    extern __shared__ float sm[];
    unsigned* Qt   = (unsigned*)(sm + SA_QT);
    unsigned* Kt   = (unsigned*)(sm + SA_KT);
    unsigned* Vt   = (unsigned*)(sm + SA_VT);
    unsigned* Psm  = (unsigned*)(sm + SA_PSM);
    float* biasH = sm + SA_BIAS;
    float* base  = sm + SA_BASE;
    float* rpt   = sm + SA_RPT;
    int*   rps   = (int*)(sm + SA_RPI);
    float* red   = sm + SA_RED;
    float* red2  = sm + SA_RED2;

    const int b = blockIdx.x;
    const int t = threadIdx.x;
    const int warpId = t >> 5, lane = t & 31;
    const int gid = lane >> 2, tid4 = lane & 3;
    const int wi = b & (NW_ - 1);
    const float* nb = nuc + (size_t)b * 49;

    // CTA-start init
    for (int idx = t; idx < 3 * 2112; idx += 256) Qt[idx] = 0u;  // Qt,Kt,Vt contiguous
    for (int idx = t; idx < 2401; idx += 256) rps[idx] = rpi[idx];
    for (int idx = t; idx < 1352; idx += 256) rpt[idx] = rpbt[idx];
    for (int idx = t; idx < 2401; idx += 256) {
        int i = idx / 49, j = idx % 49;
        base[i * 50 + j] = nb[i] + nb[j] + mask[((size_t)wi * 49 + i) * 49 + j];
    }
    // bias pad: rows >=49 -> 0 ; rows <49, cols 49..63 -> -1e30
    for (int idx = t; idx < 64 * 64; idx += 256) {
        int i = idx >> 6, j = idx & 63;
        if (i >= 49)      biasH[i * 65 + j] = 0.f;
        else if (j >= 49) biasH[i * 65 + j] = -1e30f;
    }
    __syncthreads();

    // S warp mapping: 4m x 2n halves (16x32 slab)
    const int swm  = (warpId & 3) * 16;
    const int swnh = warpId >> 2;          // 0 or 1
    const int swn  = swnh * 32;
    // PV warp mapping: 4m x 2n (16x16 slab over n=32)
    const int pwm = (warpId & 3) * 16;
    const int pwn = (warpId >> 2) * 16;

    for (int h = 0; h < HEADS_; h++) {
        const float* Qb = Q  + (size_t)b * 49 * 768 + h * 32;
        const float* Kb = KV + (size_t)b * 49 * 768 + h * 32;
        const float* Vb = KV + (size_t)b * 49 * 768 + 256 + h * 32;

        // fill tiles (rows < 49)
        for (int idx = t; idx < 49 * 32; idx += 256) {
            int i = idx >> 5, d = idx & 31;
            Qt[i * 33 + d] = f2tf(Qb[(size_t)i * 768 + d]);
            Kt[i * 33 + d] = f2tf(Kb[(size_t)i * 768 + d]);
            Vt[i * 33 + d] = f2tf(Vb[(size_t)i * 768 + d]);
        }
        // per-head bias
        for (int idx = t; idx < 2401; idx += 256) {
            int i = idx / 49, j = idx % 49;
            biasH[i * 65 + j] = base[i * 50 + j] + rpt[rps[idx] * 8 + h];
        }
        __syncthreads();

        // ---- S = Q @ K^T (m64 n64 k32) ----
        float c[4][4];
#pragma unroll
        for (int i = 0; i < 4; i++)
#pragma unroll
            for (int j = 0; j < 4; j++) c[i][j] = 0.f;

#pragma unroll
        for (int k = 0; k < 4; k++) {
            unsigned a[4];
            int r = swm + gid;
            a[0] = Qt[r * 33 + k * 8 + tid4];
            a[1] = Qt[(r + 8) * 33 + k * 8 + tid4];
            a[2] = Qt[r * 33 + k * 8 + tid4 + 4];
            a[3] = Qt[(r + 8) * 33 + k * 8 + tid4 + 4];
#pragma unroll
            for (int nt = 0; nt < 4; nt++) {
                int j = swn + nt * 8 + gid;
                unsigned bb[2];
                bb[0] = Kt[j * 33 + k * 8 + tid4];
                bb[1] = Kt[j * 33 + k * 8 + tid4 + 4];
                mma_tf32(c[nt], a, bb);
            }
        }

        // ---- bias add ----
#pragma unroll
        for (int nt = 0; nt < 4; nt++) {
            int col = swn + nt * 8 + tid4 * 2;
            int r0 = swm + gid, r1 = swm + gid + 8;
            c[nt][0] += biasH[r0 * 65 + col];
            c[nt][1] += biasH[r0 * 65 + col + 1];
            c[nt][2] += biasH[r1 * 65 + col];
            c[nt][3] += biasH[r1 * 65 + col + 1];
        }

        // ---- softmax ----
        float m0 = -1e38f, m1 = -1e38f;
#pragma unroll
        for (int nt = 0; nt < 4; nt++) {
            m0 = fmaxf(m0, fmaxf(c[nt][0], c[nt][1]));
            m1 = fmaxf(m1, fmaxf(c[nt][2], c[nt][3]));
        }
#pragma unroll
        for (int o = 1; o <= 2; o <<= 1) {
            m0 = fmaxf(m0, __shfl_xor_sync(0xffffffffu, m0, o));
            m1 = fmaxf(m1, __shfl_xor_sync(0xffffffffu, m1, o));
        }
        if (tid4 == 0) {
            red[swnh * 64 + swm + gid]     = m0;
            red[swnh * 64 + swm + gid + 8] = m1;
        }
        __syncthreads();
        m0 = fmaxf(red[swm + gid],     red[64 + swm + gid]);
        m1 = fmaxf(red[swm + gid + 8], red[64 + swm + gid + 8]);

        float s0 = 0.f, s1 = 0.f;
#pragma unroll
        for (int nt = 0; nt < 4; nt++) {
            c[nt][0] = __expf(c[nt][0] - m0);
            c[nt][1] = __expf(c[nt][1] - m0);
            c[nt][2] = __expf(c[nt][2] - m1);
            c[nt][3] = __expf(c[nt][3] - m1);
            s0 += c[nt][0] + c[nt][1];
            s1 += c[nt][2] + c[nt][3];
        }
#pragma unroll
        for (int o = 1; o <= 2; o <<= 1) {
            s0 += __shfl_xor_sync(0xffffffffu, s0, o);
            s1 += __shfl_xor_sync(0xffffffffu, s1, o);
        }
        if (tid4 == 0) {
            red2[swnh * 64 + swm + gid]     = s0;
            red2[swnh * 64 + swm + gid + 8] = s1;
        }
        __syncthreads();
        float inv0 = 1.f / (red2[swm + gid]     + red2[64 + swm + gid]);
        float inv1 = 1.f / (red2[swm + gid + 8] + red2[64 + swm + gid + 8]);

        // ---- store P to smem (tf32) ----
#pragma unroll
        for (int nt = 0; nt < 4; nt++) {
            int col = swn + nt * 8 + tid4 * 2;
            int r0 = swm + gid, r1 = swm + gid + 8;
            uint2 p0 = { f2tf(c[nt][0] * inv0), f2tf(c[nt][1] * inv0) };
            uint2 p1 = { f2tf(c[nt][2] * inv1), f2tf(c[nt][3] * inv1) };
            *(uint2*)&Psm[r0 * 66 + col] = p0;
            *(uint2*)&Psm[r1 * 66 + col] = p1;
        }
        __syncthreads();

        // ---- O = P @ V (m64 n32 k64) ----
        float c2[2][4];
#pragma unroll
        for (int i = 0; i < 2; i++)
#pragma unroll
            for (int j = 0; j < 4; j++) c2[i][j] = 0.f;

#pragma unroll
        for (int k = 0; k < 8; k++) {
            unsigned a[4];
            int r = pwm + gid;
            a[0] = Psm[r * 66 + k * 8 + tid4];
            a[1] = Psm[(r + 8) * 66 + k * 8 + tid4];
            a[2] = Psm[r * 66 + k * 8 + tid4 + 4];
            a[3] = Psm[(r + 8) * 66 + k * 8 + tid4 + 4];
#pragma unroll
            for (int nt = 0; nt < 2; nt++) {
                int d = pwn + nt * 8 + gid;
                unsigned bb[2];
                bb[0] = Vt[(k * 8 + tid4) * 33 + d];
                bb[1] = Vt[(k * 8 + tid4 + 4) * 33 + d];
                mma_tf32(c2[nt], a, bb);
            }
        }

        // ---- write O ----
        float* gOb = gO + (size_t)b * 49 * 256 + h * 32;
        int r0 = pwm + gid, r1 = pwm + gid + 8;
#pragma unroll
        for (int nt = 0; nt < 2; nt++) {
            int col = pwn + nt * 8 + tid4 * 2;
            if (r0 < 49) {
                float2 v = { c2[nt][0], c2[nt][1] };
                *(float2*)&gOb[(size_t)r0 * 256 + col] = v;
            }
            if (r1 < 49) {
                float2 v = { c2[nt][2], c2[nt][3] };
                *(float2*)&gOb[(size_t)r1 * 256 + col] = v;
            }
        }
        __syncthreads();
    }
}

// ---------------- nuclei passthrough ----------------
__global__ void copy_nuc(const float* __restrict__ in, float* __restrict__ out, int n)
{
    int i = blockIdx.x * 256 + threadIdx.x;
    if (i < n) out[i] = in[i];
}

// ---------------- launch ----------------
extern "C" void kernel_launch(void* const* d_in, const int* in_sizes, int n_in,
                              void* d_out, int out_size)
{
    const float* x        = (const float*)d_in[0];
    const float* y        = (const float*)d_in[1];
    const float* nuc      = (const float*)d_in[2];
    const float* mask     = (const float*)d_in[3];
    const float* rpbt     = (const float*)d_in[4];
    const float* qkv_w    = (const float*)d_in[5];
    const float* qkv_b    = (const float*)d_in[6];
    const float* qkv_y_w  = (const float*)d_in[7];
    const float* qkv_y_b  = (const float*)d_in[8];
    const float* proj_qx_w= (const float*)d_in[9];
    const float* proj_qx_b= (const float*)d_in[10];
    const float* proj_qy_w= (const float*)d_in[11];
    const float* proj_qy_b= (const float*)d_in[12];
    const float* proj_w   = (const float*)d_in[13];
    const float* proj_b   = (const float*)d_in[14];
    const float* proj_y_w = (const float*)d_in[15];
    const float* proj_y_b = (const float*)d_in[16];
    const int*   rpi      = (const int*)d_in[17];
    float* out = (float*)d_out;

    float *xbuf, *ybuf, *ox, *oy, *wx, *wy, *bx, *by;
    cudaGetSymbolAddress((void**)&xbuf, g_xbuf);
    cudaGetSymbolAddress((void**)&ybuf, g_ybuf);
    cudaGetSymbolAddress((void**)&ox,   g_ox);
    cudaGetSymbolAddress((void**)&oy,   g_oy);
    cudaGetSymbolAddress((void**)&wx,   g_wx);
    cudaGetSymbolAddress((void**)&wy,   g_wy);
    cudaGetSymbolAddress((void**)&bx,   g_bx);
    cudaGetSymbolAddress((void**)&by,   g_by);

    cudaFuncSetAttribute(attn_kernel, cudaFuncAttributeMaxDynamicSharedMemorySize,
                         ATTN_SMEM_BYTES);

    // weight concat (tiny)
    prep_w<<<768, 256>>>(qkv_w,   qkv_b,   proj_qx_w, proj_qx_b, wx, bx);
    prep_w<<<768, 256>>>(qkv_y_w, qkv_y_b, proj_qy_w, proj_qy_b, wy, by);

    const int mtiles = M_ROWS / 128;  // 1568

    // fused input projections: [k|v|q] per row
    gemm_tf32<<<dim3(768 / 128, mtiles), 256>>>(x, wx, bx, xbuf, 768);
    gemm_tf32<<<dim3(768 / 128, mtiles), 256>>>(y, wy, by, ybuf, 768);

    // attention cores
    attn_kernel<<<B_B, 256, ATTN_SMEM_BYTES>>>(ybuf + 512, xbuf, nuc, mask, rpbt, rpi, ox);
    attn_kernel<<<B_B, 256, ATTN_SMEM_BYTES>>>(xbuf + 512, ybuf, nuc, mask, rpbt, rpi, oy);

    // output projections
    gemm_tf32<<<dim3(256 / 128, mtiles), 256>>>(ox, proj_w,   proj_b,   out, 256);
    gemm_tf32<<<dim3(256 / 128, mtiles), 256>>>(oy, proj_y_w, proj_y_b,
                                                out + (size_t)M_ROWS * 256, 256);

    // nuclei passthrough
    copy_nuc<<<(M_ROWS + 255) / 256, 256>>>(nuc, out + 2 * (size_t)M_ROWS * 256, M_ROWS);
}

// round 5
// speedup vs baseline: 2.6112x; 1.2404x over previous
#include <cuda_runtime.h>

#define B_B 4096
#define N_TOK 49
#define DIM_ 256
#define HEADS_ 8
#define NW_ 64
#define Q_SCALE 0.17677669529663687f   // 32^-0.5
#define M_ROWS (B_B * N_TOK)           // 200704

// ---------------- scratch (device globals) ----------------
__device__ __align__(16) float g_xbuf[(size_t)M_ROWS * 768]; // k|v|q per row
__device__ __align__(16) float g_ybuf[(size_t)M_ROWS * 768];
__device__ __align__(16) float g_ox  [(size_t)M_ROWS * 256];
__device__ __align__(16) float g_oy  [(size_t)M_ROWS * 256];
__device__ __align__(16) float g_wx  [256 * 768];
__device__ __align__(16) float g_wy  [256 * 768];
__device__ __align__(16) float g_bx  [768];
__device__ __align__(16) float g_by  [768];
__device__ __align__(16) float g_rpbH[HEADS_ * 2452];        // [h][i*50+j]

// ---------------- helpers ----------------
__device__ __forceinline__ unsigned f2tf(float f) {
    unsigned u;
    asm("cvt.rna.tf32.f32 %0, %1;" : "=r"(u) : "f"(f));
    return u;
}
__device__ __forceinline__ void mma_tf32(float* c, const unsigned* a, const unsigned* b) {
    asm volatile(
        "mma.sync.aligned.m16n8k8.row.col.f32.tf32.tf32.f32 "
        "{%0,%1,%2,%3}, {%4,%5,%6,%7}, {%8,%9}, {%0,%1,%2,%3};\n"
        : "+f"(c[0]), "+f"(c[1]), "+f"(c[2]), "+f"(c[3])
        : "r"(a[0]), "r"(a[1]), "r"(a[2]), "r"(a[3]), "r"(b[0]), "r"(b[1]));
}

// ---------------- prep: weight concat + rpb gather ----------------
__global__ void prep_w(const float* __restrict__ qkv_w, const float* __restrict__ qkv_b,
                       const float* __restrict__ qw, const float* __restrict__ qb,
                       float* __restrict__ Wc, float* __restrict__ bc)
{
    int i = blockIdx.x * 256 + threadIdx.x;
    if (i < 256 * 768) {
        int r = i / 768, ccol = i % 768;
        Wc[i] = (ccol < 512) ? qkv_w[r * 512 + ccol]
                             : qw[r * 256 + (ccol - 512)] * Q_SCALE;
    }
    if (i < 768) bc[i] = (i < 512) ? qkv_b[i] : qb[i - 512] * Q_SCALE;
}

__global__ void prep_rpb(const float* __restrict__ rpbt, const int* __restrict__ rpi,
                         float* __restrict__ rpbH)
{
    int i = blockIdx.x * 256 + threadIdx.x;  // over 8*2401
    if (i < HEADS_ * 2401) {
        int h = i / 2401, ij = i % 2401;
        int r = ij / 49, j = ij % 49;
        rpbH[h * 2452 + r * 50 + j] = rpbt[rpi[ij] * 8 + h];
    }
}

// ---------------- tf32 tensor-core GEMM (unchanged from R4) ----------------
__global__ __launch_bounds__(256, 2) void gemm_tf32(
    const float* __restrict__ A, const float* __restrict__ W,
    const float* __restrict__ bias, float* __restrict__ C, int Ncol)
{
    __shared__ unsigned As[128][20];
    __shared__ unsigned Bs[16][136];

    const int t = threadIdx.x;
    const int warpId = t >> 5, lane = t & 31;
    const int gid = lane >> 2;
    const int tid4 = lane & 3;
    const int wm = (warpId & 1) * 64;
    const int wn = (warpId >> 1) * 32;
    const int tileM = blockIdx.y * 128;
    const int tileN = blockIdx.x * 128;

    const int arow = t >> 1;
    const int akq = (t & 1) * 8;
    const float* Ap = A + (size_t)(tileM + arow) * 256 + akq;
    const int bkr = t >> 4;
    const int bnc = (t & 15) * 4;
    const float* Wp = W + (size_t)bkr * Ncol + tileN + bnc;

    float c[16][4];
#pragma unroll
    for (int i = 0; i < 16; i++)
#pragma unroll
        for (int j = 0; j < 4; j++) c[i][j] = 0.f;

    float4 pa0 = *(const float4*)(Ap);
    float4 pa1 = *(const float4*)(Ap + 4);
    float4 pb0 = *(const float4*)(Wp);
    float4 pb1 = *(const float4*)(Wp + 64);

    for (int k0 = 0; k0 < 256; k0 += 16) {
        {
            uint4 ua0 = { f2tf(pa0.x), f2tf(pa0.y), f2tf(pa0.z), f2tf(pa0.w) };
            uint4 ua1 = { f2tf(pa1.x), f2tf(pa1.y), f2tf(pa1.z), f2tf(pa1.w) };
            uint4 ub0 = { f2tf(pb0.x), f2tf(pb0.y), f2tf(pb0.z), f2tf(pb0.w) };
            uint4 ub1 = { f2tf(pb1.x), f2tf(pb1.y), f2tf(pb1.z), f2tf(pb1.w) };
            *(uint4*)&As[arow][akq]      = ua0;
            *(uint4*)&As[arow][akq + 4]  = ua1;
            *(uint4*)&Bs[bkr][bnc]       = ub0;
            *(uint4*)&Bs[bkr][bnc + 64]  = ub1;
        }
        __syncthreads();

        if (k0 + 16 < 256) {
            pa0 = *(const float4*)(Ap + k0 + 16);
            pa1 = *(const float4*)(Ap + k0 + 20);
            pb0 = *(const float4*)(Wp + (size_t)(k0 + 16) * Ncol);
            pb1 = *(const float4*)(Wp + (size_t)(k0 + 16) * Ncol + 64);
        }

#pragma unroll
        for (int kh = 0; kh < 16; kh += 8) {
            unsigned a[4][4], b[4][2];
#pragma unroll
            for (int mt = 0; mt < 4; mt++) {
                int r = wm + mt * 16 + gid;
                a[mt][0] = As[r][kh + tid4];
                a[mt][1] = As[r + 8][kh + tid4];
                a[mt][2] = As[r][kh + tid4 + 4];
                a[mt][3] = As[r + 8][kh + tid4 + 4];
            }
#pragma unroll
            for (int nt = 0; nt < 4; nt++) {
                int ncol = wn + nt * 8 + gid;
                b[nt][0] = Bs[kh + tid4][ncol];
                b[nt][1] = Bs[kh + tid4 + 4][ncol];
            }
#pragma unroll
            for (int mt = 0; mt < 4; mt++)
#pragma unroll
                for (int nt = 0; nt < 4; nt++)
                    mma_tf32(c[mt * 4 + nt], a[mt], b[nt]);
        }
        __syncthreads();
    }

#pragma unroll
    for (int mt = 0; mt < 4; mt++) {
        int row = tileM + wm + mt * 16 + gid;
#pragma unroll
        for (int nt = 0; nt < 4; nt++) {
            int col = tileN + wn + nt * 8 + tid4 * 2;
            float bx = bias[col], by = bias[col + 1];
            float2 v0 = { c[mt * 4 + nt][0] + bx, c[mt * 4 + nt][1] + by };
            float2 v1 = { c[mt * 4 + nt][2] + bx, c[mt * 4 + nt][3] + by };
            *(float2*)&C[(size_t)row * Ncol + col] = v0;
            *(float2*)&C[(size_t)(row + 8) * Ncol + col] = v1;
        }
    }
}

// ---------------- tensor-core attention core (lean smem) ----------------
// grid (4096, 2): y = path. 256 threads = 8 warps. 49 padded to 64.
#define SB_QT   0                        // 64*33 = 2112
#define SB_KT   (SB_QT + 2112)
#define SB_VT   (SB_KT + 2112)
#define SB_PSM  (SB_VT + 2112)           // 64*72 = 4608 (72: conflict-free frag loads)
#define SB_BASE (SB_PSM + 4608)          // 2452
#define SB_RED  (SB_BASE + 2452)         // 128
#define SB_RED2 (SB_RED + 128)           // 128
#define SB_TOT  (SB_RED2 + 128)          // 11540 u32
#define ATTN_SMEM_BYTES (SB_TOT * 4)     // 46,160 B -> 4 CTAs/SM

__global__ __launch_bounds__(256) void attn_kernel(
    const float* __restrict__ xbuf,  // row stride 768: k|v|q
    const float* __restrict__ ybuf,
    const float* __restrict__ nuc,   // (B,49)
    const float* __restrict__ mask,  // (64,49,49)
    const float* __restrict__ rpbH,  // (8, 2452) padded bias tables
    float* __restrict__ ox,
    float* __restrict__ oy)
{
    extern __shared__ float sm[];
    unsigned* Qt  = (unsigned*)(sm + SB_QT);
    unsigned* Kt  = (unsigned*)(sm + SB_KT);
    unsigned* Vt  = (unsigned*)(sm + SB_VT);
    unsigned* Psm = (unsigned*)(sm + SB_PSM);
    float* base = sm + SB_BASE;
    float* red  = sm + SB_RED;
    float* red2 = sm + SB_RED2;

    const int b = blockIdx.x;
    const int path = blockIdx.y;
    const float* Q  = (path ? g_xbuf : g_ybuf) + 512;  // q section
    const float* KV =  path ? g_ybuf : g_xbuf;
    float* gO       =  path ? oy : ox;
    // silence unused (pointers passed for dependency clarity)
    (void)xbuf; (void)ybuf;

    const int t = threadIdx.x;
    const int warpId = t >> 5, lane = t & 31;
    const int gid = lane >> 2, tid4 = lane & 3;
    const int wi = b & (NW_ - 1);
    const float* nb = nuc + (size_t)b * 49;

    // one-time init: base bias + zero V pad rows (0 x NaN hazard in PV)
    for (int idx = t; idx < 2401; idx += 256) {
        int i = idx / 49, j = idx % 49;
        base[i * 50 + j] = nb[i] + nb[j] + mask[((size_t)wi * 49 + i) * 49 + j];
    }
    for (int idx = t; idx < 15 * 33; idx += 256) Vt[49 * 33 + idx] = 0u;
    __syncthreads();

    // S warp mapping: 4m x 2n halves (16x32 slab)
    const int swm  = (warpId & 3) * 16;
    const int swnh = warpId >> 2;          // 0 or 1
    const int swn  = swnh * 32;
    // PV warp mapping: 4m x 2n (16x16 slab over n=32)
    const int pwm = (warpId & 3) * 16;
    const int pwn = (warpId >> 2) * 16;

    const int r0s = swm + gid, r1s = r0s + 8;
    const bool v0 = r0s < 49, v1 = r1s < 49;

    for (int h = 0; h < HEADS_; h++) {
        const float* Qb = Q  + (size_t)b * 49 * 768 + h * 32;
        const float* Kb = KV + (size_t)b * 49 * 768 + h * 32;
        const float* Vb = KV + (size_t)b * 49 * 768 + 256 + h * 32;
        const float* rpb = rpbH + h * 2452;

        // fill tiles (rows < 49)
        for (int idx = t; idx < 49 * 32; idx += 256) {
            int i = idx >> 5, d = idx & 31;
            Qt[i * 33 + d] = f2tf(Qb[(size_t)i * 768 + d]);
            Kt[i * 33 + d] = f2tf(Kb[(size_t)i * 768 + d]);
            Vt[i * 33 + d] = f2tf(Vb[(size_t)i * 768 + d]);
        }
        __syncthreads();

        // ---- S = Q @ K^T (m64 n64 k32) ----
        float c[4][4];
#pragma unroll
        for (int i = 0; i < 4; i++)
#pragma unroll
            for (int j = 0; j < 4; j++) c[i][j] = 0.f;

#pragma unroll
        for (int k = 0; k < 4; k++) {
            unsigned a[4];
            a[0] = Qt[r0s * 33 + k * 8 + tid4];
            a[1] = Qt[r1s * 33 + k * 8 + tid4];
            a[2] = Qt[r0s * 33 + k * 8 + tid4 + 4];
            a[3] = Qt[r1s * 33 + k * 8 + tid4 + 4];
#pragma unroll
            for (int nt = 0; nt < 4; nt++) {
                int j = swn + nt * 8 + gid;
                unsigned bb[2];
                bb[0] = Kt[j * 33 + k * 8 + tid4];
                bb[1] = Kt[j * 33 + k * 8 + tid4 + 4];
                mma_tf32(c[nt], a, bb);
            }
        }

        // ---- bias/mask in registers ----
#pragma unroll
        for (int nt = 0; nt < 4; nt++) {
            int col = swn + nt * 8 + tid4 * 2;
            bool jc0 = col < 49, jc1 = (col + 1) < 49;
            if (v0) {
                c[nt][0] = jc0 ? c[nt][0] + base[r0s * 50 + col]     + rpb[r0s * 50 + col]     : -1e30f;
                c[nt][1] = jc1 ? c[nt][1] + base[r0s * 50 + col + 1] + rpb[r0s * 50 + col + 1] : -1e30f;
            } else { c[nt][0] = 0.f; c[nt][1] = 0.f; }
            if (v1) {
                c[nt][2] = jc0 ? c[nt][2] + base[r1s * 50 + col]     + rpb[r1s * 50 + col]     : -1e30f;
                c[nt][3] = jc1 ? c[nt][3] + base[r1s * 50 + col + 1] + rpb[r1s * 50 + col + 1] : -1e30f;
            } else { c[nt][2] = 0.f; c[nt][3] = 0.f; }
        }

        // ---- softmax, single smem round trip ----
        float m0 = -1e30f, m1 = -1e30f;
#pragma unroll
        for (int nt = 0; nt < 4; nt++) {
            m0 = fmaxf(m0, fmaxf(c[nt][0], c[nt][1]));
            m1 = fmaxf(m1, fmaxf(c[nt][2], c[nt][3]));
        }
#pragma unroll
        for (int o = 1; o <= 2; o <<= 1) {
            m0 = fmaxf(m0, __shfl_xor_sync(0xffffffffu, m0, o));
            m1 = fmaxf(m1, __shfl_xor_sync(0xffffffffu, m1, o));
        }
        float s0 = 0.f, s1 = 0.f;
#pragma unroll
        for (int nt = 0; nt < 4; nt++) {
            c[nt][0] = __expf(c[nt][0] - m0);
            c[nt][1] = __expf(c[nt][1] - m0);
            c[nt][2] = __expf(c[nt][2] - m1);
            c[nt][3] = __expf(c[nt][3] - m1);
            s0 += c[nt][0] + c[nt][1];
            s1 += c[nt][2] + c[nt][3];
        }
#pragma unroll
        for (int o = 1; o <= 2; o <<= 1) {
            s0 += __shfl_xor_sync(0xffffffffu, s0, o);
            s1 += __shfl_xor_sync(0xffffffffu, s1, o);
        }
        if (tid4 == 0) {
            red [swnh * 64 + r0s] = m0;  red [swnh * 64 + r1s] = m1;
            red2[swnh * 64 + r0s] = s0;  red2[swnh * 64 + r1s] = s1;
        }
        __syncthreads();
        {
            float mA = red[r0s], mB = red[64 + r0s];
            float M0 = fmaxf(mA, mB);
            float S0 = red2[r0s] * __expf(mA - M0) + red2[64 + r0s] * __expf(mB - M0);
            float f0 = __expf(m0 - M0) / S0;
            float mA1 = red[r1s], mB1 = red[64 + r1s];
            float M1 = fmaxf(mA1, mB1);
            float S1 = red2[r1s] * __expf(mA1 - M1) + red2[64 + r1s] * __expf(mB1 - M1);
            float f1 = __expf(m1 - M1) / S1;
#pragma unroll
            for (int nt = 0; nt < 4; nt++) {
                int col = swn + nt * 8 + tid4 * 2;
                uint2 p0 = { f2tf(c[nt][0] * f0), f2tf(c[nt][1] * f0) };
                uint2 p1 = { f2tf(c[nt][2] * f1), f2tf(c[nt][3] * f1) };
                *(uint2*)&Psm[r0s * 72 + col] = p0;
                *(uint2*)&Psm[r1s * 72 + col] = p1;
            }
        }
        __syncthreads();

        // ---- O = P @ V (m64 n32 k64) ----
        float c2[2][4];
#pragma unroll
        for (int i = 0; i < 2; i++)
#pragma unroll
            for (int j = 0; j < 4; j++) c2[i][j] = 0.f;

        const int pr0 = pwm + gid, pr1 = pr0 + 8;
#pragma unroll
        for (int k = 0; k < 8; k++) {
            unsigned a[4];
            a[0] = Psm[pr0 * 72 + k * 8 + tid4];
            a[1] = Psm[pr1 * 72 + k * 8 + tid4];
            a[2] = Psm[pr0 * 72 + k * 8 + tid4 + 4];
            a[3] = Psm[pr1 * 72 + k * 8 + tid4 + 4];
#pragma unroll
            for (int nt = 0; nt < 2; nt++) {
                int d = pwn + nt * 8 + gid;
                unsigned bb[2];
                bb[0] = Vt[(k * 8 + tid4) * 33 + d];
                bb[1] = Vt[(k * 8 + tid4 + 4) * 33 + d];
                mma_tf32(c2[nt], a, bb);
            }
        }

        // ---- write O ----
        float* gOb = gO + (size_t)b * 49 * 256 + h * 32;
#pragma unroll
        for (int nt = 0; nt < 2; nt++) {
            int col = pwn + nt * 8 + tid4 * 2;
            if (pr0 < 49) {
                float2 v = { c2[nt][0], c2[nt][1] };
                *(float2*)&gOb[(size_t)pr0 * 256 + col] = v;
            }
            if (pr1 < 49) {
                float2 v = { c2[nt][2], c2[nt][3] };
                *(float2*)&gOb[(size_t)pr1 * 256 + col] = v;
            }
        }
        __syncthreads();
    }
}

// ---------------- nuclei passthrough ----------------
__global__ void copy_nuc(const float* __restrict__ in, float* __restrict__ out, int n4)
{
    int i = blockIdx.x * 256 + threadIdx.x;
    if (i < n4) ((float4*)out)[i] = ((const float4*)in)[i];
}

// ---------------- launch ----------------
extern "C" void kernel_launch(void* const* d_in, const int* in_sizes, int n_in,
                              void* d_out, int out_size)
{
    const float* x        = (const float*)d_in[0];
    const float* y        = (const float*)d_in[1];
    const float* nuc      = (const float*)d_in[2];
    const float* mask     = (const float*)d_in[3];
    const float* rpbt     = (const float*)d_in[4];
    const float* qkv_w    = (const float*)d_in[5];
    const float* qkv_b    = (const float*)d_in[6];
    const float* qkv_y_w  = (const float*)d_in[7];
    const float* qkv_y_b  = (const float*)d_in[8];
    const float* proj_qx_w= (const float*)d_in[9];
    const float* proj_qx_b= (const float*)d_in[10];
    const float* proj_qy_w= (const float*)d_in[11];
    const float* proj_qy_b= (const float*)d_in[12];
    const float* proj_w   = (const float*)d_in[13];
    const float* proj_b   = (const float*)d_in[14];
    const float* proj_y_w = (const float*)d_in[15];
    const float* proj_y_b = (const float*)d_in[16];
    const int*   rpi      = (const int*)d_in[17];
    float* out = (float*)d_out;

    float *xbuf, *ybuf, *ox, *oy, *wx, *wy, *bx, *by, *rpbH;
    cudaGetSymbolAddress((void**)&xbuf, g_xbuf);
    cudaGetSymbolAddress((void**)&ybuf, g_ybuf);
    cudaGetSymbolAddress((void**)&ox,   g_ox);
    cudaGetSymbolAddress((void**)&oy,   g_oy);
    cudaGetSymbolAddress((void**)&wx,   g_wx);
    cudaGetSymbolAddress((void**)&wy,   g_wy);
    cudaGetSymbolAddress((void**)&bx,   g_bx);
    cudaGetSymbolAddress((void**)&by,   g_by);
    cudaGetSymbolAddress((void**)&rpbH, g_rpbH);

    cudaFuncSetAttribute(attn_kernel, cudaFuncAttributeMaxDynamicSharedMemorySize,
                         ATTN_SMEM_BYTES);

    // prep (tiny)
    prep_w<<<768, 256>>>(qkv_w,   qkv_b,   proj_qx_w, proj_qx_b, wx, bx);
    prep_w<<<768, 256>>>(qkv_y_w, qkv_y_b, proj_qy_w, proj_qy_b, wy, by);
    prep_rpb<<<(HEADS_ * 2401 + 255) / 256, 256>>>(rpbt, rpi, rpbH);

    const int mtiles = M_ROWS / 128;  // 1568

    // fused input projections: [k|v|q] per row
    gemm_tf32<<<dim3(768 / 128, mtiles), 256>>>(x, wx, bx, xbuf, 768);
    gemm_tf32<<<dim3(768 / 128, mtiles), 256>>>(y, wy, by, ybuf, 768);

    // attention (both paths, one launch)
    attn_kernel<<<dim3(B_B, 2), 256, ATTN_SMEM_BYTES>>>(xbuf, ybuf, nuc, mask, rpbH, ox, oy);

    // output projections
    gemm_tf32<<<dim3(256 / 128, mtiles), 256>>>(ox, proj_w,   proj_b,   out, 256);
    gemm_tf32<<<dim3(256 / 128, mtiles), 256>>>(oy, proj_y_w, proj_y_b,
                                                out + (size_t)M_ROWS * 256, 256);

    // nuclei passthrough (200704 floats = 50176 float4)
    copy_nuc<<<(M_ROWS / 4 + 255) / 256, 256>>>(nuc, out + 2 * (size_t)M_ROWS * 256,
                                                M_ROWS / 4);
}

// round 7
// speedup vs baseline: 3.4120x; 1.3066x over previous
#include <cuda_runtime.h>
#include <cstdint>

#define B_B 4096
#define N_TOK 49
#define HEADS_ 8
#define NW_ 64
#define Q_SCALE 0.17677669529663687f
#define M_ROWS (B_B * N_TOK)           // 200704 = 1568 * 128

// ---------------- scratch ----------------
__device__ __align__(16) float g_xbuf[(size_t)M_ROWS * 768];
__device__ __align__(16) float g_ybuf[(size_t)M_ROWS * 768];
__device__ __align__(16) float g_ox  [(size_t)M_ROWS * 256];
__device__ __align__(16) float g_oy  [(size_t)M_ROWS * 256];
__device__ __align__(16) float g_wx  [256 * 768];
__device__ __align__(16) float g_wy  [256 * 768];
__device__ __align__(16) float g_pw  [256 * 256];
__device__ __align__(16) float g_py  [256 * 256];
__device__ __align__(16) float g_bx  [768];
__device__ __align__(16) float g_by  [768];
__device__ __align__(16) float g_rpbH[HEADS_ * 2452];

// ---------------- helpers ----------------
__device__ __forceinline__ unsigned f2tf(float f) {
    unsigned u; asm("cvt.rna.tf32.f32 %0, %1;" : "=r"(u) : "f"(f)); return u;
}
__device__ __forceinline__ uint32_t smem_u32(const void* p) {
    uint32_t a;
    asm("{ .reg .u64 t; cvta.to.shared.u64 t, %1; cvt.u32.u64 %0, t; }" : "=r"(a) : "l"(p));
    return a;
}
__device__ __forceinline__ void mma_tf32(float* c, const unsigned* a, const unsigned* b) {
    asm volatile(
        "mma.sync.aligned.m16n8k8.row.col.f32.tf32.tf32.f32 "
        "{%0,%1,%2,%3}, {%4,%5,%6,%7}, {%8,%9}, {%0,%1,%2,%3};\n"
        : "+f"(c[0]), "+f"(c[1]), "+f"(c[2]), "+f"(c[3])
        : "r"(a[0]), "r"(a[1]), "r"(a[2]), "r"(a[3]), "r"(b[0]), "r"(b[1]));
}
__device__ __forceinline__ void cpasync16(uint32_t dst, const void* src) {
    asm volatile("cp.async.cg.shared.global [%0], [%1], 16;" :: "r"(dst), "l"(src));
}
#define CP_COMMIT() asm volatile("cp.async.commit_group;" ::: "memory")

// ---------------- prep ----------------
// Wc[256][768] k-major, rna-rounded: [qkv_w | q_w * SCALE]
__global__ void prep_w(const float* __restrict__ qkv_w, const float* __restrict__ qkv_b,
                       const float* __restrict__ qw, const float* __restrict__ qb,
                       float* __restrict__ Wc, float* __restrict__ bc)
{
    int i = blockIdx.x * 256 + threadIdx.x;
    if (i < 256 * 768) {
        int k = i / 768, n = i % 768;
        float v = (n < 512) ? qkv_w[k * 512 + n] : qw[k * 256 + (n - 512)] * Q_SCALE;
        Wc[i] = __uint_as_float(f2tf(v));
    }
    if (i < 768) bc[i] = (i < 512) ? qkv_b[i] : qb[i - 512] * Q_SCALE;
}
__global__ void prep_p(const float* __restrict__ W, float* __restrict__ Wr)
{
    int i = blockIdx.x * 256 + threadIdx.x;
    if (i < 65536) Wr[i] = __uint_as_float(f2tf(W[i]));
}
__global__ void prep_rpb(const float* __restrict__ rpbt, const int* __restrict__ rpi,
                         float* __restrict__ rpbH)
{
    int i = blockIdx.x * 256 + threadIdx.x;
    if (i < HEADS_ * 2401) {
        int h = i / 2401, ij = i % 2401;
        int r = ij / 49, j = ij % 49;
        rpbH[h * 2452 + r * 50 + j] = rpbt[rpi[ij] * 8 + h];
    }
}

// ---------------- tf32 mma.sync GEMM, warp tile 64x64 ----------------
// C[M,Ncol] = A[M,256] @ W[256,Ncol] + bias. W pre-rounded tf32, k-major.
// CTA 128x128, 128 threads = 4 warps (2m x 2n), K-tile 32, B double-buffered cp.async.
// smem (words): As[128][36]=4608 | Bs0[32][136]=4352 | Bs1=4352  -> 13312 w = 53248 B
#define GW_AS   0
#define GW_BS0  4608
#define GW_BS1  8960
#define GW_TOTW 13312
#define GEMM_SMEM_BYTES (GW_TOTW * 4)

template<int ROUND>
__global__ __launch_bounds__(128) void gemm_tf32(
    const float* __restrict__ A, const float* __restrict__ W,
    const float* __restrict__ bias, float* __restrict__ C, int Ncol)
{
    extern __shared__ unsigned smg[];
    unsigned* As = smg + GW_AS;
    const uint32_t sb = smem_u32(smg);

    const int t = threadIdx.x;
    const int warpId = t >> 5, lane = t & 31;
    const int gid = lane >> 2, tid4 = lane & 3;
    const int wm = (warpId & 1) * 64;
    const int wn = (warpId >> 1) * 64;
    const size_t tileM = (size_t)blockIdx.y * 128;
    const int tileN = blockIdx.x * 128;

    // A mapping: unit i: row = (t>>3) + i*16, quad q = t&7 (coalesced 128B/8 lanes)
    const int arow0 = t >> 3;
    const int aq = t & 7;
    const float* Ap = A + (tileM + arow0) * 256 + aq * 4;

    // B mapping: unit i: kr = (t>>5) + i*4, col quad nc4 = t&31 (fully coalesced)
    const int bkr0 = t >> 5;
    const int bnc4 = t & 31;
    const float* Wp = W + (size_t)bkr0 * Ncol + tileN + bnc4 * 4;

    float acc[4][8][4];
#pragma unroll
    for (int i = 0; i < 4; i++)
#pragma unroll
        for (int j = 0; j < 8; j++)
#pragma unroll
            for (int l = 0; l < 4; l++) acc[i][j][l] = 0.f;

    // prologue: A tile 0 into regs; B tiles 0,1 via cp.async
    float4 pa[8];
#pragma unroll
    for (int i = 0; i < 8; i++)
        pa[i] = *(const float4*)(Ap + (size_t)(i * 16) * 256);

#pragma unroll
    for (int s = 0; s < 2; s++) {
        uint32_t bdst = sb + (s ? GW_BS1 : GW_BS0) * 4;
        const float* src = Wp + (size_t)(s * 32) * Ncol;
#pragma unroll
        for (int i = 0; i < 8; i++)
            cpasync16(bdst + (uint32_t)(((bkr0 + i * 4) * 136 + bnc4 * 4) * 4),
                      src + (size_t)(i * 4) * Ncol);
        CP_COMMIT();
    }

    for (int c = 0; c < 8; c++) {
        // commit prefetched A regs to smem (rna tf32)
#pragma unroll
        for (int i = 0; i < 8; i++) {
            uint4 ua = { f2tf(pa[i].x), f2tf(pa[i].y), f2tf(pa[i].z), f2tf(pa[i].w) };
            *(uint4*)&As[(arow0 + i * 16) * 36 + aq * 4] = ua;
        }
        if (c < 7) asm volatile("cp.async.wait_group 1;" ::: "memory");
        else       asm volatile("cp.async.wait_group 0;" ::: "memory");
        __syncthreads();

        if (c < 7) {
            const float* Ap2 = Ap + (c + 1) * 32;
#pragma unroll
            for (int i = 0; i < 8; i++)
                pa[i] = *(const float4*)(Ap2 + (size_t)(i * 16) * 256);
        }

        const unsigned* Bs = smg + ((c & 1) ? GW_BS1 : GW_BS0);
#pragma unroll
        for (int kh = 0; kh < 32; kh += 8) {
            unsigned a[4][4];
#pragma unroll
            for (int mt = 0; mt < 4; mt++) {
                int r = wm + mt * 16 + gid;
                a[mt][0] = As[r * 36 + kh + tid4];
                a[mt][1] = As[(r + 8) * 36 + kh + tid4];
                a[mt][2] = As[r * 36 + kh + tid4 + 4];
                a[mt][3] = As[(r + 8) * 36 + kh + tid4 + 4];
            }
#pragma unroll
            for (int nt = 0; nt < 8; nt++) {
                int ncol = wn + nt * 8 + gid;
                unsigned b[2];
                b[0] = Bs[(kh + tid4) * 136 + ncol];
                b[1] = Bs[(kh + tid4 + 4) * 136 + ncol];
#pragma unroll
                for (int mt = 0; mt < 4; mt++)
                    mma_tf32(acc[mt][nt], a[mt], b);
            }
        }
        __syncthreads();

        if (c < 6) {
            uint32_t bdst = sb + ((c & 1) ? GW_BS1 : GW_BS0) * 4;
            const float* src = Wp + (size_t)((c + 2) * 32) * Ncol;
#pragma unroll
            for (int i = 0; i < 8; i++)
                cpasync16(bdst + (uint32_t)(((bkr0 + i * 4) * 136 + bnc4 * 4) * 4),
                          src + (size_t)(i * 4) * Ncol);
            CP_COMMIT();
        }
    }

    // epilogue
#pragma unroll
    for (int mt = 0; mt < 4; mt++) {
        size_t row0 = tileM + wm + mt * 16 + gid;
#pragma unroll
        for (int nt = 0; nt < 8; nt++) {
            int col = tileN + wn + nt * 8 + tid4 * 2;
            float b0 = bias[col], b1 = bias[col + 1];
            float o0 = acc[mt][nt][0] + b0, o1 = acc[mt][nt][1] + b1;
            float o2 = acc[mt][nt][2] + b0, o3 = acc[mt][nt][3] + b1;
            if (ROUND) {
                o0 = __uint_as_float(f2tf(o0)); o1 = __uint_as_float(f2tf(o1));
                o2 = __uint_as_float(f2tf(o2)); o3 = __uint_as_float(f2tf(o3));
            }
            float2 v0 = { o0, o1 }, v1 = { o2, o3 };
            *(float2*)&C[row0 * Ncol + col] = v0;
            *(float2*)&C[(row0 + 8) * Ncol + col] = v1;
        }
    }
}

// ---------------- attention (conflict-free strides) ----------------
// Qt/Kt stride 36 (bank = gid*4+tid4, bijective), Vt stride 40 (tid4*8+gid),
// Psm stride 72 (gid*8+tid4 / tid4*8+gid).
#define SB_QT   0                        // 64*36 = 2304
#define SB_KT   (SB_QT + 2304)
#define SB_VT   (SB_KT + 2304)           // 64*40 = 2560
#define SB_PSM  (SB_VT + 2560)           // 64*72 = 4608
#define SB_BASE (SB_PSM + 4608)          // 2452
#define SB_RED  (SB_BASE + 2452)
#define SB_RED2 (SB_RED + 128)
#define SB_TOT  (SB_RED2 + 128)          // 14484 words
#define ATTN_SMEM_BYTES (SB_TOT * 4)     // 57,936 B

__global__ __launch_bounds__(256) void attn_kernel(
    const float* __restrict__ nuc, const float* __restrict__ mask,
    const float* __restrict__ rpbH, float* __restrict__ ox, float* __restrict__ oy)
{
    extern __shared__ float sm[];
    unsigned* Qt  = (unsigned*)(sm + SB_QT);
    unsigned* Kt  = (unsigned*)(sm + SB_KT);
    unsigned* Vt  = (unsigned*)(sm + SB_VT);
    unsigned* Psm = (unsigned*)(sm + SB_PSM);
    float* base = sm + SB_BASE;
    float* red  = sm + SB_RED;
    float* red2 = sm + SB_RED2;

    const int b = blockIdx.x;
    const int path = blockIdx.y;
    const float* Q  = (path ? g_xbuf : g_ybuf) + 512;
    const float* KV =  path ? g_ybuf : g_xbuf;
    float* gO       =  path ? oy : ox;

    const int t = threadIdx.x;
    const int warpId = t >> 5, lane = t & 31;
    const int gid = lane >> 2, tid4 = lane & 3;
    const int wi = b & (NW_ - 1);
    const float* nb = nuc + (size_t)b * 49;

    for (int idx = t; idx < 2401; idx += 256) {
        int i = idx / 49, j = idx % 49;
        base[i * 50 + j] = nb[i] + nb[j] + mask[((size_t)wi * 49 + i) * 49 + j];
    }
    for (int idx = t; idx < 15 * 40; idx += 256) Vt[49 * 40 + idx] = 0u;
    __syncthreads();

    const int swm  = (warpId & 3) * 16;
    const int swnh = warpId >> 2;
    const int swn  = swnh * 32;
    const int pwm  = (warpId & 3) * 16;
    const int pwn  = (warpId >> 2) * 16;

    const int r0s = swm + gid, r1s = r0s + 8;
    const bool v0 = r0s < 49, v1 = r1s < 49;

    for (int h = 0; h < HEADS_; h++) {
        const float* Qb = Q  + (size_t)b * 49 * 768 + h * 32;
        const float* Kb = KV + (size_t)b * 49 * 768 + h * 32;
        const float* Vb = KV + (size_t)b * 49 * 768 + 256 + h * 32;
        const float* rpb = rpbH + h * 2452;

        for (int idx = t; idx < 49 * 32; idx += 256) {
            int i = idx >> 5, d = idx & 31;
            Qt[i * 36 + d] = __float_as_uint(Qb[(size_t)i * 768 + d]);
            Kt[i * 36 + d] = __float_as_uint(Kb[(size_t)i * 768 + d]);
            Vt[i * 40 + d] = __float_as_uint(Vb[(size_t)i * 768 + d]);
        }
        __syncthreads();

        // S = Q @ K^T
        float c[4][4];
#pragma unroll
        for (int i = 0; i < 4; i++)
#pragma unroll
            for (int j = 0; j < 4; j++) c[i][j] = 0.f;
#pragma unroll
        for (int k = 0; k < 4; k++) {
            unsigned a[4];
            a[0] = Qt[r0s * 36 + k * 8 + tid4];
            a[1] = Qt[r1s * 36 + k * 8 + tid4];
            a[2] = Qt[r0s * 36 + k * 8 + tid4 + 4];
            a[3] = Qt[r1s * 36 + k * 8 + tid4 + 4];
#pragma unroll
            for (int nt = 0; nt < 4; nt++) {
                int j = swn + nt * 8 + gid;
                unsigned bb[2];
                bb[0] = Kt[j * 36 + k * 8 + tid4];
                bb[1] = Kt[j * 36 + k * 8 + tid4 + 4];
                mma_tf32(c[nt], a, bb);
            }
        }

        // bias/mask in registers
#pragma unroll
        for (int nt = 0; nt < 4; nt++) {
            int col = swn + nt * 8 + tid4 * 2;
            bool jc0 = col < 49, jc1 = (col + 1) < 49;
            if (v0) {
                c[nt][0] = jc0 ? c[nt][0] + base[r0s * 50 + col]     + rpb[r0s * 50 + col]     : -1e30f;
                c[nt][1] = jc1 ? c[nt][1] + base[r0s * 50 + col + 1] + rpb[r0s * 50 + col + 1] : -1e30f;
            } else { c[nt][0] = 0.f; c[nt][1] = 0.f; }
            if (v1) {
                c[nt][2] = jc0 ? c[nt][2] + base[r1s * 50 + col]     + rpb[r1s * 50 + col]     : -1e30f;
                c[nt][3] = jc1 ? c[nt][3] + base[r1s * 50 + col + 1] + rpb[r1s * 50 + col + 1] : -1e30f;
            } else { c[nt][2] = 0.f; c[nt][3] = 0.f; }
        }

        // softmax (single smem round trip)
        float m0 = -1e30f, m1 = -1e30f;
#pragma unroll
        for (int nt = 0; nt < 4; nt++) {
            m0 = fmaxf(m0, fmaxf(c[nt][0], c[nt][1]));
            m1 = fmaxf(m1, fmaxf(c[nt][2], c[nt][3]));
        }
#pragma unroll
        for (int o = 1; o <= 2; o <<= 1) {
            m0 = fmaxf(m0, __shfl_xor_sync(0xffffffffu, m0, o));
            m1 = fmaxf(m1, __shfl_xor_sync(0xffffffffu, m1, o));
        }
        float s0 = 0.f, s1 = 0.f;
#pragma unroll
        for (int nt = 0; nt < 4; nt++) {
            c[nt][0] = __expf(c[nt][0] - m0);
            c[nt][1] = __expf(c[nt][1] - m0);
            c[nt][2] = __expf(c[nt][2] - m1);
            c[nt][3] = __expf(c[nt][3] - m1);
            s0 += c[nt][0] + c[nt][1];
            s1 += c[nt][2] + c[nt][3];
        }
#pragma unroll
        for (int o = 1; o <= 2; o <<= 1) {
            s0 += __shfl_xor_sync(0xffffffffu, s0, o);
            s1 += __shfl_xor_sync(0xffffffffu, s1, o);
        }
        if (tid4 == 0) {
            red [swnh * 64 + r0s] = m0;  red [swnh * 64 + r1s] = m1;
            red2[swnh * 64 + r0s] = s0;  red2[swnh * 64 + r1s] = s1;
        }
        __syncthreads();
        {
            float mA = red[r0s], mB = red[64 + r0s];
            float M0 = fmaxf(mA, mB);
            float S0 = red2[r0s] * __expf(mA - M0) + red2[64 + r0s] * __expf(mB - M0);
            float f0 = __expf(m0 - M0) / S0;
            float mA1 = red[r1s], mB1 = red[64 + r1s];
            float M1 = fmaxf(mA1, mB1);
            float S1 = red2[r1s] * __expf(mA1 - M1) + red2[64 + r1s] * __expf(mB1 - M1);
            float f1 = __expf(m1 - M1) / S1;
#pragma unroll
            for (int nt = 0; nt < 4; nt++) {
                int col = swn + nt * 8 + tid4 * 2;
                uint2 p0 = { f2tf(c[nt][0] * f0), f2tf(c[nt][1] * f0) };
                uint2 p1 = { f2tf(c[nt][2] * f1), f2tf(c[nt][3] * f1) };
                *(uint2*)&Psm[r0s * 72 + col] = p0;
                *(uint2*)&Psm[r1s * 72 + col] = p1;
            }
        }
        __syncthreads();

        // O = P @ V
        float c2[2][4];
#pragma unroll
        for (int i = 0; i < 2; i++)
#pragma unroll
            for (int j = 0; j < 4; j++) c2[i][j] = 0.f;

        const int pr0 = pwm + gid, pr1 = pr0 + 8;
#pragma unroll
        for (int k = 0; k < 8; k++) {
            unsigned a[4];
            a[0] = Psm[pr0 * 72 + k * 8 + tid4];
            a[1] = Psm[pr1 * 72 + k * 8 + tid4];
            a[2] = Psm[pr0 * 72 + k * 8 + tid4 + 4];
            a[3] = Psm[pr1 * 72 + k * 8 + tid4 + 4];
#pragma unroll
            for (int nt = 0; nt < 2; nt++) {
                int d = pwn + nt * 8 + gid;
                unsigned bb[2];
                bb[0] = Vt[(k * 8 + tid4) * 40 + d];
                bb[1] = Vt[(k * 8 + tid4 + 4) * 40 + d];
                mma_tf32(c2[nt], a, bb);
            }
        }

        // write O (rna-rounded: feeds tf32 output GEMM)
        float* gOb = gO + (size_t)b * 49 * 256 + h * 32;
#pragma unroll
        for (int nt = 0; nt < 2; nt++) {
            int col = pwn + nt * 8 + tid4 * 2;
            if (pr0 < 49) {
                float2 v = { __uint_as_float(f2tf(c2[nt][0])), __uint_as_float(f2tf(c2[nt][1])) };
                *(float2*)&gOb[(size_t)pr0 * 256 + col] = v;
            }
            if (pr1 < 49) {
                float2 v = { __uint_as_float(f2tf(c2[nt][2])), __uint_as_float(f2tf(c2[nt][3])) };
                *(float2*)&gOb[(size_t)pr1 * 256 + col] = v;
            }
        }
        __syncthreads();
    }
}

// ---------------- nuclei passthrough ----------------
__global__ void copy_nuc(const float* __restrict__ in, float* __restrict__ out, int n4)
{
    int i = blockIdx.x * 256 + threadIdx.x;
    if (i < n4) ((float4*)out)[i] = ((const float4*)in)[i];
}

// ---------------- launch ----------------
extern "C" void kernel_launch(void* const* d_in, const int* in_sizes, int n_in,
                              void* d_out, int out_size)
{
    const float* x        = (const float*)d_in[0];
    const float* y        = (const float*)d_in[1];
    const float* nuc      = (const float*)d_in[2];
    const float* mask     = (const float*)d_in[3];
    const float* rpbt     = (const float*)d_in[4];
    const float* qkv_w    = (const float*)d_in[5];
    const float* qkv_b    = (const float*)d_in[6];
    const float* qkv_y_w  = (const float*)d_in[7];
    const float* qkv_y_b  = (const float*)d_in[8];
    const float* proj_qx_w= (const float*)d_in[9];
    const float* proj_qx_b= (const float*)d_in[10];
    const float* proj_qy_w= (const float*)d_in[11];
    const float* proj_qy_b= (const float*)d_in[12];
    const float* proj_w   = (const float*)d_in[13];
    const float* proj_b   = (const float*)d_in[14];
    const float* proj_y_w = (const float*)d_in[15];
    const float* proj_y_b = (const float*)d_in[16];
    const int*   rpi      = (const int*)d_in[17];
    float* out = (float*)d_out;

    float *xbuf, *ybuf, *ox, *oy, *wx, *wy, *pw, *py, *bx, *by, *rpbH;
    cudaGetSymbolAddress((void**)&xbuf, g_xbuf);
    cudaGetSymbolAddress((void**)&ybuf, g_ybuf);
    cudaGetSymbolAddress((void**)&ox,   g_ox);
    cudaGetSymbolAddress((void**)&oy,   g_oy);
    cudaGetSymbolAddress((void**)&wx,   g_wx);
    cudaGetSymbolAddress((void**)&wy,   g_wy);
    cudaGetSymbolAddress((void**)&pw,   g_pw);
    cudaGetSymbolAddress((void**)&py,   g_py);
    cudaGetSymbolAddress((void**)&bx,   g_bx);
    cudaGetSymbolAddress((void**)&by,   g_by);
    cudaGetSymbolAddress((void**)&rpbH, g_rpbH);

    cudaFuncSetAttribute(attn_kernel, cudaFuncAttributeMaxDynamicSharedMemorySize,
                         ATTN_SMEM_BYTES);
    cudaFuncSetAttribute((const void*)gemm_tf32<1>, cudaFuncAttributeMaxDynamicSharedMemorySize,
                         GEMM_SMEM_BYTES);
    cudaFuncSetAttribute((const void*)gemm_tf32<0>, cudaFuncAttributeMaxDynamicSharedMemorySize,
                         GEMM_SMEM_BYTES);

    // prep (tiny)
    prep_w<<<768, 256>>>(qkv_w,   qkv_b,   proj_qx_w, proj_qx_b, wx, bx);
    prep_w<<<768, 256>>>(qkv_y_w, qkv_y_b, proj_qy_w, proj_qy_b, wy, by);
    prep_p<<<256, 256>>>(proj_w,   pw);
    prep_p<<<256, 256>>>(proj_y_w, py);
    prep_rpb<<<(HEADS_ * 2401 + 255) / 256, 256>>>(rpbt, rpi, rpbH);

    const int mtiles = M_ROWS / 128;  // 1568

    // input projections: outputs pre-rounded tf32 (attention consumes raw)
    gemm_tf32<1><<<dim3(6, mtiles), 128, GEMM_SMEM_BYTES>>>(x, wx, bx, xbuf, 768);
    gemm_tf32<1><<<dim3(6, mtiles), 128, GEMM_SMEM_BYTES>>>(y, wy, by, ybuf, 768);

    // attention (both paths)
    attn_kernel<<<dim3(B_B, 2), 256, ATTN_SMEM_BYTES>>>(nuc, mask, rpbH, ox, oy);

    // output projections (final output raw fp32)
    gemm_tf32<0><<<dim3(2, mtiles), 128, GEMM_SMEM_BYTES>>>(ox, pw, proj_b, out, 256);
    gemm_tf32<0><<<dim3(2, mtiles), 128, GEMM_SMEM_BYTES>>>(oy, py, proj_y_b,
                                                            out + (size_t)M_ROWS * 256, 256);

    copy_nuc<<<(M_ROWS / 4 + 255) / 256, 256>>>(nuc, out + 2 * (size_t)M_ROWS * 256,
                                                M_ROWS / 4);
}

// round 8
// speedup vs baseline: 4.1543x; 1.2176x over previous
#include <cuda_runtime.h>
#include <cstdint>

#define B_B 4096
#define N_TOK 49
#define HEADS_ 8
#define NW_ 64
#define Q_SCALE 0.17677669529663687f
#define M_ROWS (B_B * N_TOK)           // 200704 = 1568 * 128

// ---------------- scratch ----------------
__device__ __align__(16) float g_xbuf[(size_t)M_ROWS * 768];
__device__ __align__(16) float g_ybuf[(size_t)M_ROWS * 768];
__device__ __align__(16) float g_ox  [(size_t)M_ROWS * 256];
__device__ __align__(16) float g_oy  [(size_t)M_ROWS * 256];
__device__ __align__(16) float g_wx  [256 * 768];
__device__ __align__(16) float g_wy  [256 * 768];
__device__ __align__(16) float g_pw  [256 * 256];
__device__ __align__(16) float g_py  [256 * 256];
__device__ __align__(16) float g_bx  [768];
__device__ __align__(16) float g_by  [768];
__device__ __align__(16) float g_rpbH[HEADS_ * 2452];

// ---------------- helpers ----------------
__device__ __forceinline__ unsigned f2tf(float f) {
    unsigned u; asm("cvt.rna.tf32.f32 %0, %1;" : "=r"(u) : "f"(f)); return u;
}
__device__ __forceinline__ uint32_t smem_u32(const void* p) {
    uint32_t a;
    asm("{ .reg .u64 t; cvta.to.shared.u64 t, %1; cvt.u32.u64 %0, t; }" : "=r"(a) : "l"(p));
    return a;
}
__device__ __forceinline__ void mma_tf32(float* c, const unsigned* a, const unsigned* b) {
    asm volatile(
        "mma.sync.aligned.m16n8k8.row.col.f32.tf32.tf32.f32 "
        "{%0,%1,%2,%3}, {%4,%5,%6,%7}, {%8,%9}, {%0,%1,%2,%3};\n"
        : "+f"(c[0]), "+f"(c[1]), "+f"(c[2]), "+f"(c[3])
        : "r"(a[0]), "r"(a[1]), "r"(a[2]), "r"(a[3]), "r"(b[0]), "r"(b[1]));
}
__device__ __forceinline__ void cpasync16(uint32_t dst, const void* src) {
    asm volatile("cp.async.cg.shared.global [%0], [%1], 16;" :: "r"(dst), "l"(src));
}
#define CP_COMMIT() asm volatile("cp.async.commit_group;" ::: "memory")

// ---------------- prep ----------------
__global__ void prep_w(const float* __restrict__ qkv_w, const float* __restrict__ qkv_b,
                       const float* __restrict__ qw, const float* __restrict__ qb,
                       float* __restrict__ Wc, float* __restrict__ bc)
{
    int i = blockIdx.x * 256 + threadIdx.x;
    if (i < 256 * 768) {
        int k = i / 768, n = i % 768;
        float v = (n < 512) ? qkv_w[k * 512 + n] : qw[k * 256 + (n - 512)] * Q_SCALE;
        Wc[i] = __uint_as_float(f2tf(v));
    }
    if (i < 768) bc[i] = (i < 512) ? qkv_b[i] : qb[i - 512] * Q_SCALE;
}
__global__ void prep_p(const float* __restrict__ W, float* __restrict__ Wr)
{
    int i = blockIdx.x * 256 + threadIdx.x;
    if (i < 65536) Wr[i] = __uint_as_float(f2tf(W[i]));
}
__global__ void prep_rpb(const float* __restrict__ rpbt, const int* __restrict__ rpi,
                         float* __restrict__ rpbH)
{
    int i = blockIdx.x * 256 + threadIdx.x;
    if (i < HEADS_ * 2401) {
        int h = i / 2401, ij = i % 2401;
        int r = ij / 49, j = ij % 49;
        rpbH[h * 2452 + r * 50 + j] = rpbt[rpi[ij] * 8 + h];
    }
}

// ---------------- tf32 mma.sync GEMM, warp tile 64x64, dual-problem ----------
#define GW_AS   0
#define GW_BS0  4608
#define GW_BS1  8960
#define GW_TOTW 13312
#define GEMM_SMEM_BYTES (GW_TOTW * 4)

template<int ROUND>
__global__ __launch_bounds__(128) void gemm_tf32(
    const float* __restrict__ A0, const float* __restrict__ W0,
    const float* __restrict__ b0, float* __restrict__ C0,
    const float* __restrict__ A1, const float* __restrict__ W1,
    const float* __restrict__ b1, float* __restrict__ C1, int Ncol)
{
    extern __shared__ unsigned smg[];
    unsigned* As = smg + GW_AS;
    const uint32_t sb = smem_u32(smg);

    const float* A    = blockIdx.z ? A1 : A0;
    const float* W    = blockIdx.z ? W1 : W0;
    const float* bias = blockIdx.z ? b1 : b0;
    float*       C    = blockIdx.z ? C1 : C0;

    const int t = threadIdx.x;
    const int warpId = t >> 5, lane = t & 31;
    const int gid = lane >> 2, tid4 = lane & 3;
    const int wm = (warpId & 1) * 64;
    const int wn = (warpId >> 1) * 64;
    const size_t tileM = (size_t)blockIdx.y * 128;
    const int tileN = blockIdx.x * 128;

    const int arow0 = t >> 3;
    const int aq = t & 7;
    const float* Ap = A + (tileM + arow0) * 256 + aq * 4;

    const int bkr0 = t >> 5;
    const int bnc4 = t & 31;
    const float* Wp = W + (size_t)bkr0 * Ncol + tileN + bnc4 * 4;

    float acc[4][8][4];
#pragma unroll
    for (int i = 0; i < 4; i++)
#pragma unroll
        for (int j = 0; j < 8; j++)
#pragma unroll
            for (int l = 0; l < 4; l++) acc[i][j][l] = 0.f;

    float4 pa[8];
#pragma unroll
    for (int i = 0; i < 8; i++)
        pa[i] = *(const float4*)(Ap + (size_t)(i * 16) * 256);

#pragma unroll
    for (int s = 0; s < 2; s++) {
        uint32_t bdst = sb + (s ? GW_BS1 : GW_BS0) * 4;
        const float* src = Wp + (size_t)(s * 32) * Ncol;
#pragma unroll
        for (int i = 0; i < 8; i++)
            cpasync16(bdst + (uint32_t)(((bkr0 + i * 4) * 136 + bnc4 * 4) * 4),
                      src + (size_t)(i * 4) * Ncol);
        CP_COMMIT();
    }

    for (int c = 0; c < 8; c++) {
#pragma unroll
        for (int i = 0; i < 8; i++) {
            uint4 ua = { f2tf(pa[i].x), f2tf(pa[i].y), f2tf(pa[i].z), f2tf(pa[i].w) };
            *(uint4*)&As[(arow0 + i * 16) * 36 + aq * 4] = ua;
        }
        if (c < 7) asm volatile("cp.async.wait_group 1;" ::: "memory");
        else       asm volatile("cp.async.wait_group 0;" ::: "memory");
        __syncthreads();

        if (c < 7) {
            const float* Ap2 = Ap + (c + 1) * 32;
#pragma unroll
            for (int i = 0; i < 8; i++)
                pa[i] = *(const float4*)(Ap2 + (size_t)(i * 16) * 256);
        }

        const unsigned* Bs = smg + ((c & 1) ? GW_BS1 : GW_BS0);
#pragma unroll
        for (int kh = 0; kh < 32; kh += 8) {
            unsigned a[4][4];
#pragma unroll
            for (int mt = 0; mt < 4; mt++) {
                int r = wm + mt * 16 + gid;
                a[mt][0] = As[r * 36 + kh + tid4];
                a[mt][1] = As[(r + 8) * 36 + kh + tid4];
                a[mt][2] = As[r * 36 + kh + tid4 + 4];
                a[mt][3] = As[(r + 8) * 36 + kh + tid4 + 4];
            }
#pragma unroll
            for (int nt = 0; nt < 8; nt++) {
                int ncol = wn + nt * 8 + gid;
                unsigned b[2];
                b[0] = Bs[(kh + tid4) * 136 + ncol];
                b[1] = Bs[(kh + tid4 + 4) * 136 + ncol];
#pragma unroll
                for (int mt = 0; mt < 4; mt++)
                    mma_tf32(acc[mt][nt], a[mt], b);
            }
        }
        __syncthreads();

        if (c < 6) {
            uint32_t bdst = sb + ((c & 1) ? GW_BS1 : GW_BS0) * 4;
            const float* src = Wp + (size_t)((c + 2) * 32) * Ncol;
#pragma unroll
            for (int i = 0; i < 8; i++)
                cpasync16(bdst + (uint32_t)(((bkr0 + i * 4) * 136 + bnc4 * 4) * 4),
                          src + (size_t)(i * 4) * Ncol);
            CP_COMMIT();
        }
    }

#pragma unroll
    for (int mt = 0; mt < 4; mt++) {
        size_t row0 = tileM + wm + mt * 16 + gid;
#pragma unroll
        for (int nt = 0; nt < 8; nt++) {
            int col = tileN + wn + nt * 8 + tid4 * 2;
            float bb0 = bias[col], bb1 = bias[col + 1];
            float o0 = acc[mt][nt][0] + bb0, o1 = acc[mt][nt][1] + bb1;
            float o2 = acc[mt][nt][2] + bb0, o3 = acc[mt][nt][3] + bb1;
            if (ROUND) {
                o0 = __uint_as_float(f2tf(o0)); o1 = __uint_as_float(f2tf(o1));
                o2 = __uint_as_float(f2tf(o2)); o3 = __uint_as_float(f2tf(o3));
            }
            float2 v0 = { o0, o1 }, v1 = { o2, o3 };
            *(float2*)&C[row0 * Ncol + col] = v0;
            *(float2*)&C[(row0 + 8) * Ncol + col] = v1;
        }
    }
}

// ---------------- attention: double-buffered head pipeline ----------------
// Per buffer (7168 words): Qt[64*36] | Kt[64*36] | Vt[64*40]; P aliases Qt|Kt
// region with stride 68 (64*68=4352 <= 4608). Two buffers + base + red.
#define AB_BUF1 7168
#define AB_BASE 14336                   // 2452
#define AB_RED  (AB_BASE + 2452)        // 128
#define AB_RED2 (AB_RED + 128)          // 128
#define AB_TOT  (AB_RED2 + 128)         // 17044 words
#define ATTN_SMEM_BYTES (AB_TOT * 4)    // 68,176 B -> 3 CTAs/SM

__device__ __forceinline__ void fill_head(uint32_t sb, int bufw,
    const float* Qb, const float* Kb, const float* Vb, int t)
{
    for (int u = t; u < 1176; u += 256) {
        int tz = u / 392, rem = u - tz * 392;
        int row = rem >> 3, c4 = rem & 7;
        uint32_t dstw; const float* src;
        if (tz == 0)      { dstw = bufw + row * 36 + c4 * 4;        src = Qb + row * 768 + c4 * 4; }
        else if (tz == 1) { dstw = bufw + 2304 + row * 36 + c4 * 4; src = Kb + row * 768 + c4 * 4; }
        else              { dstw = bufw + 4608 + row * 40 + c4 * 4; src = Vb + row * 768 + c4 * 4; }
        cpasync16(sb + dstw * 4, src);
    }
}

__global__ __launch_bounds__(256) void attn_kernel(
    const float* __restrict__ nuc, const float* __restrict__ mask,
    const float* __restrict__ rpbH, float* __restrict__ ox, float* __restrict__ oy)
{
    extern __shared__ float sm[];
    const uint32_t sb = smem_u32(sm);
    unsigned* smw = (unsigned*)sm;
    float* base = sm + AB_BASE;
    float* red  = sm + AB_RED;
    float* red2 = sm + AB_RED2;

    const int b = blockIdx.x;
    const int path = blockIdx.y;
    const float* Q  = (path ? g_xbuf : g_ybuf) + 512 + (size_t)b * 49 * 768;
    const float* KV = (path ? g_ybuf : g_xbuf) + (size_t)b * 49 * 768;
    float* gO       = (path ? g_oy : g_ox) + (size_t)b * 49 * 256;

    const int t = threadIdx.x;
    const int warpId = t >> 5, lane = t & 31;
    const int gid = lane >> 2, tid4 = lane & 3;
    const int wi = b & (NW_ - 1);
    const float* nb = nuc + (size_t)b * 49;

    // prologue: start head-0 fill immediately
    fill_head(sb, 0, Q, KV, KV + 256, t);
    CP_COMMIT();

    // one-time init: base table + zero V pad rows in both buffers
    for (int idx = t; idx < 2401; idx += 256) {
        int i = idx / 49, j = idx % 49;
        base[i * 50 + j] = nb[i] + nb[j] + mask[((size_t)wi * 49 + i) * 49 + j];
    }
    for (int idx = t; idx < 15 * 40; idx += 256) {
        smw[4608 + 49 * 40 + idx] = 0u;            // buf0 Vt pads
        smw[AB_BUF1 + 4608 + 49 * 40 + idx] = 0u;  // buf1 Vt pads
    }

    const int swm  = (warpId & 3) * 16;
    const int swnh = warpId >> 2;
    const int swn  = swnh * 32;
    const int pwm  = (warpId & 3) * 16;
    const int pwn  = (warpId >> 2) * 16;

    const int r0s = swm + gid, r1s = r0s + 8;
    const bool v0 = r0s < 49, v1 = r1s < 49;

    for (int h = 0; h < HEADS_; h++) {
        const int curw = (h & 1) ? AB_BUF1 : 0;
        asm volatile("cp.async.wait_group 0;" ::: "memory");
        __syncthreads();   // tiles[cur] ready; prev PV done -> nxt buffer reusable

        if (h < 7) {
            const int nxtw = (h & 1) ? 0 : AB_BUF1;
            fill_head(sb, nxtw, Q + (h + 1) * 32, KV + (h + 1) * 32,
                      KV + 256 + (h + 1) * 32, t);
            CP_COMMIT();
        }

        const unsigned* Qt = smw + curw;
        const unsigned* Kt = smw + curw + 2304;
        const unsigned* Vt = smw + curw + 4608;
        unsigned* Psm = smw + curw;            // aliases Qt|Kt, stride 68
        const float* rpb = rpbH + h * 2452;

        // ---- S = Q @ K^T ----
        float c[4][4];
#pragma unroll
        for (int i = 0; i < 4; i++)
#pragma unroll
            for (int j = 0; j < 4; j++) c[i][j] = 0.f;
#pragma unroll
        for (int k = 0; k < 4; k++) {
            unsigned a[4];
            a[0] = Qt[r0s * 36 + k * 8 + tid4];
            a[1] = Qt[r1s * 36 + k * 8 + tid4];
            a[2] = Qt[r0s * 36 + k * 8 + tid4 + 4];
            a[3] = Qt[r1s * 36 + k * 8 + tid4 + 4];
#pragma unroll
            for (int nt = 0; nt < 4; nt++) {
                int j = swn + nt * 8 + gid;
                unsigned bb[2];
                bb[0] = Kt[j * 36 + k * 8 + tid4];
                bb[1] = Kt[j * 36 + k * 8 + tid4 + 4];
                mma_tf32(c[nt], a, bb);
            }
        }

        // ---- bias/mask in registers ----
#pragma unroll
        for (int nt = 0; nt < 4; nt++) {
            int col = swn + nt * 8 + tid4 * 2;
            bool jc0 = col < 49, jc1 = (col + 1) < 49;
            if (v0) {
                c[nt][0] = jc0 ? c[nt][0] + base[r0s * 50 + col]     + rpb[r0s * 50 + col]     : -1e30f;
                c[nt][1] = jc1 ? c[nt][1] + base[r0s * 50 + col + 1] + rpb[r0s * 50 + col + 1] : -1e30f;
            } else { c[nt][0] = 0.f; c[nt][1] = 0.f; }
            if (v1) {
                c[nt][2] = jc0 ? c[nt][2] + base[r1s * 50 + col]     + rpb[r1s * 50 + col]     : -1e30f;
                c[nt][3] = jc1 ? c[nt][3] + base[r1s * 50 + col + 1] + rpb[r1s * 50 + col + 1] : -1e30f;
            } else { c[nt][2] = 0.f; c[nt][3] = 0.f; }
        }

        // ---- softmax (single smem round trip) ----
        float m0 = -1e30f, m1 = -1e30f;
#pragma unroll
        for (int nt = 0; nt < 4; nt++) {
            m0 = fmaxf(m0, fmaxf(c[nt][0], c[nt][1]));
            m1 = fmaxf(m1, fmaxf(c[nt][2], c[nt][3]));
        }
#pragma unroll
        for (int o = 1; o <= 2; o <<= 1) {
            m0 = fmaxf(m0, __shfl_xor_sync(0xffffffffu, m0, o));
            m1 = fmaxf(m1, __shfl_xor_sync(0xffffffffu, m1, o));
        }
        float s0 = 0.f, s1 = 0.f;
#pragma unroll
        for (int nt = 0; nt < 4; nt++) {
            c[nt][0] = __expf(c[nt][0] - m0);
            c[nt][1] = __expf(c[nt][1] - m0);
            c[nt][2] = __expf(c[nt][2] - m1);
            c[nt][3] = __expf(c[nt][3] - m1);
            s0 += c[nt][0] + c[nt][1];
            s1 += c[nt][2] + c[nt][3];
        }
#pragma unroll
        for (int o = 1; o <= 2; o <<= 1) {
            s0 += __shfl_xor_sync(0xffffffffu, s0, o);
            s1 += __shfl_xor_sync(0xffffffffu, s1, o);
        }
        if (tid4 == 0) {
            red [swnh * 64 + r0s] = m0;  red [swnh * 64 + r1s] = m1;
            red2[swnh * 64 + r0s] = s0;  red2[swnh * 64 + r1s] = s1;
        }
        __syncthreads();   // also orders all S-phase frag reads before P writes
        {
            float mA = red[r0s], mB = red[64 + r0s];
            float M0 = fmaxf(mA, mB);
            float S0 = red2[r0s] * __expf(mA - M0) + red2[64 + r0s] * __expf(mB - M0);
            float f0 = __expf(m0 - M0) / S0;
            float mA1 = red[r1s], mB1 = red[64 + r1s];
            float M1 = fmaxf(mA1, mB1);
            float S1 = red2[r1s] * __expf(mA1 - M1) + red2[64 + r1s] * __expf(mB1 - M1);
            float f1 = __expf(m1 - M1) / S1;
#pragma unroll
            for (int nt = 0; nt < 4; nt++) {
                int col = swn + nt * 8 + tid4 * 2;
                uint2 p0 = { f2tf(c[nt][0] * f0), f2tf(c[nt][1] * f0) };
                uint2 p1 = { f2tf(c[nt][2] * f1), f2tf(c[nt][3] * f1) };
                *(uint2*)&Psm[r0s * 68 + col] = p0;
                *(uint2*)&Psm[r1s * 68 + col] = p1;
            }
        }
        __syncthreads();

        // ---- O = P @ V ----
        float c2[2][4];
#pragma unroll
        for (int i = 0; i < 2; i++)
#pragma unroll
            for (int j = 0; j < 4; j++) c2[i][j] = 0.f;

        const int pr0 = pwm + gid, pr1 = pr0 + 8;
#pragma unroll
        for (int k = 0; k < 8; k++) {
            unsigned a[4];
            a[0] = Psm[pr0 * 68 + k * 8 + tid4];
            a[1] = Psm[pr1 * 68 + k * 8 + tid4];
            a[2] = Psm[pr0 * 68 + k * 8 + tid4 + 4];
            a[3] = Psm[pr1 * 68 + k * 8 + tid4 + 4];
#pragma unroll
            for (int nt = 0; nt < 2; nt++) {
                int d = pwn + nt * 8 + gid;
                unsigned bb[2];
                bb[0] = Vt[(k * 8 + tid4) * 40 + d];
                bb[1] = Vt[(k * 8 + tid4 + 4) * 40 + d];
                mma_tf32(c2[nt], a, bb);
            }
        }

        // ---- write O (rna-rounded: feeds tf32 output GEMM) ----
        float* gOb = gO + h * 32;
#pragma unroll
        for (int nt = 0; nt < 2; nt++) {
            int col = pwn + nt * 8 + tid4 * 2;
            if (pr0 < 49) {
                float2 v = { __uint_as_float(f2tf(c2[nt][0])), __uint_as_float(f2tf(c2[nt][1])) };
                *(float2*)&gOb[(size_t)pr0 * 256 + col] = v;
            }
            if (pr1 < 49) {
                float2 v = { __uint_as_float(f2tf(c2[nt][2])), __uint_as_float(f2tf(c2[nt][3])) };
                *(float2*)&gOb[(size_t)pr1 * 256 + col] = v;
            }
        }
        // next iteration's top barrier orders buffer reuse after PV reads
    }
}

// ---------------- nuclei passthrough ----------------
__global__ void copy_nuc(const float* __restrict__ in, float* __restrict__ out, int n4)
{
    int i = blockIdx.x * 256 + threadIdx.x;
    if (i < n4) ((float4*)out)[i] = ((const float4*)in)[i];
}

// ---------------- launch ----------------
extern "C" void kernel_launch(void* const* d_in, const int* in_sizes, int n_in,
                              void* d_out, int out_size)
{
    const float* x        = (const float*)d_in[0];
    const float* y        = (const float*)d_in[1];
    const float* nuc      = (const float*)d_in[2];
    const float* mask     = (const float*)d_in[3];
    const float* rpbt     = (const float*)d_in[4];
    const float* qkv_w    = (const float*)d_in[5];
    const float* qkv_b    = (const float*)d_in[6];
    const float* qkv_y_w  = (const float*)d_in[7];
    const float* qkv_y_b  = (const float*)d_in[8];
    const float* proj_qx_w= (const float*)d_in[9];
    const float* proj_qx_b= (const float*)d_in[10];
    const float* proj_qy_w= (const float*)d_in[11];
    const float* proj_qy_b= (const float*)d_in[12];
    const float* proj_w   = (const float*)d_in[13];
    const float* proj_b   = (const float*)d_in[14];
    const float* proj_y_w = (const float*)d_in[15];
    const float* proj_y_b = (const float*)d_in[16];
    const int*   rpi      = (const int*)d_in[17];
    float* out = (float*)d_out;

    float *xbuf, *ybuf, *ox, *oy, *wx, *wy, *pw, *py, *bx, *by, *rpbH;
    cudaGetSymbolAddress((void**)&xbuf, g_xbuf);
    cudaGetSymbolAddress((void**)&ybuf, g_ybuf);
    cudaGetSymbolAddress((void**)&ox,   g_ox);
    cudaGetSymbolAddress((void**)&oy,   g_oy);
    cudaGetSymbolAddress((void**)&wx,   g_wx);
    cudaGetSymbolAddress((void**)&wy,   g_wy);
    cudaGetSymbolAddress((void**)&pw,   g_pw);
    cudaGetSymbolAddress((void**)&py,   g_py);
    cudaGetSymbolAddress((void**)&bx,   g_bx);
    cudaGetSymbolAddress((void**)&by,   g_by);
    cudaGetSymbolAddress((void**)&rpbH, g_rpbH);

    cudaFuncSetAttribute(attn_kernel, cudaFuncAttributeMaxDynamicSharedMemorySize,
                         ATTN_SMEM_BYTES);
    cudaFuncSetAttribute((const void*)gemm_tf32<1>, cudaFuncAttributeMaxDynamicSharedMemorySize,
                         GEMM_SMEM_BYTES);
    cudaFuncSetAttribute((const void*)gemm_tf32<0>, cudaFuncAttributeMaxDynamicSharedMemorySize,
                         GEMM_SMEM_BYTES);

    // prep (tiny)
    prep_w<<<768, 256>>>(qkv_w,   qkv_b,   proj_qx_w, proj_qx_b, wx, bx);
    prep_w<<<768, 256>>>(qkv_y_w, qkv_y_b, proj_qy_w, proj_qy_b, wy, by);
    prep_p<<<256, 256>>>(proj_w,   pw);
    prep_p<<<256, 256>>>(proj_y_w, py);
    prep_rpb<<<(HEADS_ * 2401 + 255) / 256, 256>>>(rpbt, rpi, rpbH);

    const int mtiles = M_ROWS / 128;  // 1568

    // input projections, both streams in one launch
    gemm_tf32<1><<<dim3(6, mtiles, 2), 128, GEMM_SMEM_BYTES>>>(
        x, wx, bx, xbuf, y, wy, by, ybuf, 768);

    // attention (both paths)
    attn_kernel<<<dim3(B_B, 2), 256, ATTN_SMEM_BYTES>>>(nuc, mask, rpbH, ox, oy);

    // output projections, both in one launch
    gemm_tf32<0><<<dim3(2, mtiles, 2), 128, GEMM_SMEM_BYTES>>>(
        ox, pw, proj_b, out, oy, py, proj_y_b, out + (size_t)M_ROWS * 256, 256);

    copy_nuc<<<(M_ROWS / 4 + 255) / 256, 256>>>(nuc, out + 2 * (size_t)M_ROWS * 256,
                                                M_ROWS / 4);
}

// round 9
// speedup vs baseline: 5.2734x; 1.2694x over previous
#include <cuda_runtime.h>
#include <cuda_fp16.h>
#include <cstdint>

#define B_B 4096
#define N_TOK 49
#define HEADS_ 8
#define NW_ 64
#define Q_SCALE 0.17677669529663687f
#define M_ROWS (B_B * N_TOK)           // 200704 = 1568 * 128

// ---------------- scratch ----------------
__device__ __align__(16) __half g_xbuf[(size_t)M_ROWS * 768];  // k|v|q fp16
__device__ __align__(16) __half g_ybuf[(size_t)M_ROWS * 768];
__device__ __align__(16) __half g_ox  [(size_t)M_ROWS * 256];
__device__ __align__(16) __half g_oy  [(size_t)M_ROWS * 256];
__device__ __align__(16) __half g_wx  [768 * 256];  // W^T [n][k] fp16
__device__ __align__(16) __half g_wy  [768 * 256];
__device__ __align__(16) __half g_pw  [256 * 256];
__device__ __align__(16) __half g_py  [256 * 256];
__device__ __align__(16) float  g_bx  [768];
__device__ __align__(16) float  g_by  [768];
__device__ __align__(16) float  g_rpbH[HEADS_ * 2452];

// ---------------- helpers ----------------
__device__ __forceinline__ uint32_t smem_u32(const void* p) {
    uint32_t a;
    asm("{ .reg .u64 t; cvta.to.shared.u64 t, %1; cvt.u32.u64 %0, t; }" : "=r"(a) : "l"(p));
    return a;
}
__device__ __forceinline__ unsigned packh2(float a, float b) {
    __half2 h = __floats2half2_rn(a, b);      // .x = a (low), .y = b (high)
    return *(unsigned*)&h;
}
__device__ __forceinline__ void mma_f16(float* c, const unsigned* a, const unsigned* b) {
    asm volatile(
        "mma.sync.aligned.m16n8k16.row.col.f32.f16.f16.f32 "
        "{%0,%1,%2,%3}, {%4,%5,%6,%7}, {%8,%9}, {%0,%1,%2,%3};\n"
        : "+f"(c[0]), "+f"(c[1]), "+f"(c[2]), "+f"(c[3])
        : "r"(a[0]), "r"(a[1]), "r"(a[2]), "r"(a[3]), "r"(b[0]), "r"(b[1]));
}
__device__ __forceinline__ void cpasync16(uint32_t dst, const void* src) {
    asm volatile("cp.async.cg.shared.global [%0], [%1], 16;" :: "r"(dst), "l"(src));
}
#define CP_COMMIT() asm volatile("cp.async.commit_group;" ::: "memory")

// ---------------- prep ----------------
// W^T[768][256] fp16: col n of [qkv_w | q_w*SCALE] becomes row n (K-contiguous)
__global__ void prep_w(const float* __restrict__ qkv_w, const float* __restrict__ qkv_b,
                       const float* __restrict__ qw, const float* __restrict__ qb,
                       __half* __restrict__ WT, float* __restrict__ bc)
{
    int i = blockIdx.x * 256 + threadIdx.x;
    if (i < 768 * 256) {
        int n = i >> 8, k = i & 255;
        float v = (n < 512) ? qkv_w[k * 512 + n] : qw[k * 256 + (n - 512)] * Q_SCALE;
        WT[i] = __float2half_rn(v);
    }
    if (i < 768) bc[i] = (i < 512) ? qkv_b[i] : qb[i - 512] * Q_SCALE;
}
__global__ void prep_p(const float* __restrict__ W, __half* __restrict__ WT)
{
    int i = blockIdx.x * 256 + threadIdx.x;
    if (i < 65536) { int n = i >> 8, k = i & 255; WT[i] = __float2half_rn(W[k * 256 + n]); }
}
__global__ void prep_rpb(const float* __restrict__ rpbt, const int* __restrict__ rpi,
                         float* __restrict__ rpbH)
{
    int i = blockIdx.x * 256 + threadIdx.x;
    if (i < HEADS_ * 2401) {
        int h = i / 2401, ij = i % 2401;
        int r = ij / 49, j = ij % 49;
        rpbH[h * 2452 + r * 50 + j] = rpbt[rpi[ij] * 8 + h];
    }
}

// ---------------- fp16 mma GEMM, warp tile 64x64, dual-problem ----------------
// C = A[M,256] @ W^T' + bias. AFP16=0: A fp32 (reg-cvt), C fp16. AFP16=1: A fp16
// cp.async, C fp32. smem uints: As0 0 | As1 2560 | Bs0 5120 | Bs1 7680 (stride 20).
#define GH_AS0  0
#define GH_AS1  2560
#define GH_BS0  5120
#define GH_BS1  7680
#define GEMM_SMEM_BYTES (10240 * 4)

template<int AFP16>
__global__ __launch_bounds__(128) void gemm_h(
    const void* __restrict__ A0v, const __half* __restrict__ W0,
    const float* __restrict__ b0, void* __restrict__ C0v,
    const void* __restrict__ A1v, const __half* __restrict__ W1,
    const float* __restrict__ b1, void* __restrict__ C1v, int Ncol)
{
    extern __shared__ unsigned smg[];
    const uint32_t sb = smem_u32(smg);

    const void*  Av   = blockIdx.z ? A1v : A0v;
    const __half* W   = blockIdx.z ? W1 : W0;
    const float* bias = blockIdx.z ? b1 : b0;
    void*        Cv   = blockIdx.z ? C1v : C0v;

    const int t = threadIdx.x;
    const int warpId = t >> 5, lane = t & 31;
    const int gid = lane >> 2, tid4 = lane & 3;
    const int wm = (warpId & 1) * 64;
    const int wn = (warpId >> 1) * 64;
    const size_t tileM = (size_t)blockIdx.y * 128;
    const int tileN = blockIdx.x * 128;

    float acc[4][8][4];
#pragma unroll
    for (int i = 0; i < 4; i++)
#pragma unroll
        for (int j = 0; j < 8; j++)
#pragma unroll
            for (int l = 0; l < 4; l++) acc[i][j][l] = 0.f;

    // B fill lambda-ish (macro): W^T row (tileN+r), chunk c -> 64B = 4x16B
#define GH_BFILL(stage, ch) do {                                                     \
    uint32_t bs_ = sb + ((stage) ? GH_BS1 : GH_BS0) * 4;                             \
    const __half* wsrc_ = W + (size_t)(tileN + t) * 256 + (ch) * 32;                 \
    _Pragma("unroll")                                                                \
    for (int cc = 0; cc < 4; cc++)                                                   \
        cpasync16(bs_ + (uint32_t)((t * 20 + cc * 4) * 4), wsrc_ + cc * 8);          \
} while (0)
#define GH_AFILL16(stage, ch) do {                                                   \
    uint32_t as_ = sb + ((stage) ? GH_AS1 : GH_AS0) * 4;                             \
    const __half* asrc_ = (const __half*)Av + (tileM + t) * 256 + (ch) * 32;         \
    _Pragma("unroll")                                                                \
    for (int cc = 0; cc < 4; cc++)                                                   \
        cpasync16(as_ + (uint32_t)((t * 20 + cc * 4) * 4), asrc_ + cc * 8);          \
} while (0)

    const int arow0 = t >> 3, aq = t & 7;
    const float* Af = (const float*)Av;
    float4 pa[8];

    if (AFP16) {
        GH_AFILL16(0, 0); GH_BFILL(0, 0); CP_COMMIT();
        GH_AFILL16(1, 1); GH_BFILL(1, 1); CP_COMMIT();
    } else {
#pragma unroll
        for (int i = 0; i < 8; i++)
            pa[i] = *(const float4*)(Af + (tileM + arow0 + i * 16) * 256 + aq * 4);
        GH_BFILL(0, 0); CP_COMMIT();
        GH_BFILL(1, 1); CP_COMMIT();
    }

    for (int c = 0; c < 8; c++) {
        const int s = c & 1;
        unsigned* As = smg + (s ? GH_AS1 : GH_AS0);
        const unsigned* Bs = smg + (s ? GH_BS1 : GH_BS0);

        if (!AFP16) {
#pragma unroll
            for (int i = 0; i < 8; i++) {
                uint2 u = { packh2(pa[i].x, pa[i].y), packh2(pa[i].z, pa[i].w) };
                *(uint2*)&As[(arow0 + i * 16) * 20 + aq * 2] = u;
            }
        }
        if (c < 7) asm volatile("cp.async.wait_group 1;" ::: "memory");
        else       asm volatile("cp.async.wait_group 0;" ::: "memory");
        __syncthreads();

        if (!AFP16 && c < 7) {
#pragma unroll
            for (int i = 0; i < 8; i++)
                pa[i] = *(const float4*)(Af + (tileM + arow0 + i * 16) * 256
                                         + (c + 1) * 32 + aq * 4);
        }

#pragma unroll
        for (int ks = 0; ks < 2; ks++) {
            unsigned a[4][4];
#pragma unroll
            for (int mt = 0; mt < 4; mt++) {
                int r = wm + mt * 16 + gid;
                a[mt][0] = As[r * 20 + ks * 8 + tid4];
                a[mt][1] = As[(r + 8) * 20 + ks * 8 + tid4];
                a[mt][2] = As[r * 20 + ks * 8 + tid4 + 4];
                a[mt][3] = As[(r + 8) * 20 + ks * 8 + tid4 + 4];
            }
#pragma unroll
            for (int nt = 0; nt < 8; nt++) {
                int n = wn + nt * 8 + gid;
                unsigned b[2];
                b[0] = Bs[n * 20 + ks * 8 + tid4];
                b[1] = Bs[n * 20 + ks * 8 + tid4 + 4];
#pragma unroll
                for (int mt = 0; mt < 4; mt++)
                    mma_f16(acc[mt][nt], a[mt], b);
            }
        }
        __syncthreads();

        if (c < 6) {
            if (AFP16) GH_AFILL16(s, c + 2);
            GH_BFILL(s, c + 2);
            CP_COMMIT();
        }
    }

    // epilogue
#pragma unroll
    for (int mt = 0; mt < 4; mt++) {
        size_t row0 = tileM + wm + mt * 16 + gid;
#pragma unroll
        for (int nt = 0; nt < 8; nt++) {
            int col = tileN + wn + nt * 8 + tid4 * 2;
            float bb0 = bias[col], bb1 = bias[col + 1];
            float o0 = acc[mt][nt][0] + bb0, o1 = acc[mt][nt][1] + bb1;
            float o2 = acc[mt][nt][2] + bb0, o3 = acc[mt][nt][3] + bb1;
            if (AFP16) {  // final fp32 output
                float* C = (float*)Cv;
                float2 v0 = { o0, o1 }, v1 = { o2, o3 };
                *(float2*)&C[row0 * Ncol + col] = v0;
                *(float2*)&C[(row0 + 8) * Ncol + col] = v1;
            } else {      // intermediate fp16
                __half* C = (__half*)Cv;
                *(unsigned*)&C[row0 * Ncol + col] = packh2(o0, o1);
                *(unsigned*)&C[(row0 + 8) * Ncol + col] = packh2(o2, o3);
            }
        }
    }
}

// ---------------- attention, fp16 tiles ----------------
// smem uints: stage0 [Qt 64x20 | Kt 64x20] = 2560 | stage1 2560 | Vt 32x36 = 1152
// then floats: base 2452 | red 128 | red2 128.  Psm aliases current stage (64x36).
#define AT_ST0  0
#define AT_ST1  2560
#define AT_VT   5120
#define AT_BASE 6272
#define AT_RED  (AT_BASE + 2452)
#define AT_RED2 (AT_RED + 128)
#define AT_TOT  (AT_RED2 + 128)          // 8980 words
#define ATTN_SMEM_BYTES (AT_TOT * 4)     // 35,920 B

__device__ __forceinline__ void fill_qk(uint32_t sb, int stw,
    const __half* Qb, const __half* Kb, int t)
{
    for (int u = t; u < 392; u += 256) {
        int tz = u / 196, rem = u - tz * 196;
        int row = rem >> 2, cc = rem & 3;
        uint32_t dstw = stw + (tz ? 1280 : 0) + row * 20 + cc * 4;
        const __half* src = (tz ? Kb : Qb) + row * 768 + cc * 8;
        cpasync16(sb + dstw * 4, src);
    }
}

__global__ __launch_bounds__(256) void attn_kernel(
    const float* __restrict__ nuc, const float* __restrict__ mask,
    const float* __restrict__ rpbH)
{
    extern __shared__ float sm[];
    const uint32_t sb = smem_u32(sm);
    unsigned* smw = (unsigned*)sm;
    __half* Vt_h = (__half*)(smw + AT_VT);
    float* base = sm + AT_BASE;
    float* red  = sm + AT_RED;
    float* red2 = sm + AT_RED2;

    const int b = blockIdx.x;
    const int path = blockIdx.y;
    const __half* Q  = (path ? g_xbuf : g_ybuf) + 512 + (size_t)b * 49 * 768;
    const __half* KV = (path ? g_ybuf : g_xbuf) + (size_t)b * 49 * 768;
    __half* gO       = (path ? g_oy : g_ox) + (size_t)b * 49 * 256;

    const int t = threadIdx.x;
    const int warpId = t >> 5, lane = t & 31;
    const int gid = lane >> 2, tid4 = lane & 3;
    const int wi = b & (NW_ - 1);
    const float* nb = nuc + (size_t)b * 49;

    // prologue: head-0 Q/K fill
    fill_qk(sb, AT_ST0, Q, KV, t);
    CP_COMMIT();

    // one-time init: base table + zero Vt (pads stay 0 forever)
    for (int idx = t; idx < 2401; idx += 256) {
        int i = idx / 49, j = idx % 49;
        base[i * 50 + j] = nb[i] + nb[j] + mask[((size_t)wi * 49 + i) * 49 + j];
    }
    for (int idx = t; idx < 1152; idx += 256) smw[AT_VT + idx] = 0u;

    const int swm  = (warpId & 3) * 16;
    const int swnh = warpId >> 2;
    const int swn  = swnh * 32;
    const int pwm  = (warpId & 3) * 16;
    const int pwn  = (warpId >> 2) * 16;

    const int r0s = swm + gid, r1s = r0s + 8;
    const bool v0 = r0s < 49, v1 = r1s < 49;

    // V-unit decode for this thread (u = t, t+256)
    const int vj0 = t >> 3, vdg0 = t & 7;
    const int u1 = t + 256;
    const bool hasu1 = u1 < 392;
    const int vj1 = u1 >> 3, vdg1 = u1 & 7;

    for (int h = 0; h < HEADS_; h++) {
        const int stw = (h & 1) ? AT_ST1 : AT_ST0;
        asm volatile("cp.async.wait_group 0;" ::: "memory");
        __syncthreads();   // Q/K[cur] ready; prev head fully done

        if (h < 7)
            fill_qk(sb, (h & 1) ? AT_ST0 : AT_ST1,
                    Q + (h + 1) * 32, KV + (h + 1) * 32, t);
        CP_COMMIT();       // (empty group when h==7 is harmless)

        // V LDG for current head (consumed after softmax)
        const __half* Vb = KV + 256 + h * 32;
        uint2 vr0 = *(const uint2*)(Vb + vj0 * 768 + vdg0 * 4);
        uint2 vr1 = hasu1 ? *(const uint2*)(Vb + vj1 * 768 + vdg1 * 4)
                          : make_uint2(0u, 0u);

        const unsigned* Qt = smw + stw;
        const unsigned* Kt = smw + stw + 1280;
        unsigned* Psm = smw + stw;             // aliases Qt|Kt, stride 36
        const unsigned* Vt = smw + AT_VT;      // [d][j] stride 36
        const float* rpb = rpbH + h * 2452;

        // ---- S = Q @ K^T (fp16 k16) ----
        float c[4][4];
#pragma unroll
        for (int i = 0; i < 4; i++)
#pragma unroll
            for (int j = 0; j < 4; j++) c[i][j] = 0.f;
#pragma unroll
        for (int ks = 0; ks < 2; ks++) {
            unsigned a[4];
            a[0] = Qt[r0s * 20 + ks * 8 + tid4];
            a[1] = Qt[r1s * 20 + ks * 8 + tid4];
            a[2] = Qt[r0s * 20 + ks * 8 + tid4 + 4];
            a[3] = Qt[r1s * 20 + ks * 8 + tid4 + 4];
#pragma unroll
            for (int nt = 0; nt < 4; nt++) {
                int j = swn + nt * 8 + gid;
                unsigned bb[2];
                bb[0] = Kt[j * 20 + ks * 8 + tid4];
                bb[1] = Kt[j * 20 + ks * 8 + tid4 + 4];
                mma_f16(c[nt], a, bb);
            }
        }

        // ---- bias/mask in registers ----
#pragma unroll
        for (int nt = 0; nt < 4; nt++) {
            int col = swn + nt * 8 + tid4 * 2;
            bool jc0 = col < 49, jc1 = (col + 1) < 49;
            if (v0) {
                c[nt][0] = jc0 ? c[nt][0] + base[r0s * 50 + col]     + rpb[r0s * 50 + col]     : -1e30f;
                c[nt][1] = jc1 ? c[nt][1] + base[r0s * 50 + col + 1] + rpb[r0s * 50 + col + 1] : -1e30f;
            } else { c[nt][0] = 0.f; c[nt][1] = 0.f; }
            if (v1) {
                c[nt][2] = jc0 ? c[nt][2] + base[r1s * 50 + col]     + rpb[r1s * 50 + col]     : -1e30f;
                c[nt][3] = jc1 ? c[nt][3] + base[r1s * 50 + col + 1] + rpb[r1s * 50 + col + 1] : -1e30f;
            } else { c[nt][2] = 0.f; c[nt][3] = 0.f; }
        }

        // ---- softmax (single smem round trip) ----
        float m0 = -1e30f, m1 = -1e30f;
#pragma unroll
        for (int nt = 0; nt < 4; nt++) {
            m0 = fmaxf(m0, fmaxf(c[nt][0], c[nt][1]));
            m1 = fmaxf(m1, fmaxf(c[nt][2], c[nt][3]));
        }
#pragma unroll
        for (int o = 1; o <= 2; o <<= 1) {
            m0 = fmaxf(m0, __shfl_xor_sync(0xffffffffu, m0, o));
            m1 = fmaxf(m1, __shfl_xor_sync(0xffffffffu, m1, o));
        }
        float s0 = 0.f, s1 = 0.f;
#pragma unroll
        for (int nt = 0; nt < 4; nt++) {
            c[nt][0] = __expf(c[nt][0] - m0);
            c[nt][1] = __expf(c[nt][1] - m0);
            c[nt][2] = __expf(c[nt][2] - m1);
            c[nt][3] = __expf(c[nt][3] - m1);
            s0 += c[nt][0] + c[nt][1];
            s1 += c[nt][2] + c[nt][3];
        }
#pragma unroll
        for (int o = 1; o <= 2; o <<= 1) {
            s0 += __shfl_xor_sync(0xffffffffu, s0, o);
            s1 += __shfl_xor_sync(0xffffffffu, s1, o);
        }
        if (tid4 == 0) {
            red [swnh * 64 + r0s] = m0;  red [swnh * 64 + r1s] = m1;
            red2[swnh * 64 + r0s] = s0;  red2[swnh * 64 + r1s] = s1;
        }
        __syncthreads();   // orders all S frag reads before P/V smem writes
        {
            float mA = red[r0s], mB = red[64 + r0s];
            float M0 = fmaxf(mA, mB);
            float S0 = red2[r0s] * __expf(mA - M0) + red2[64 + r0s] * __expf(mB - M0);
            float f0 = __expf(m0 - M0) / S0;
            float mA1 = red[r1s], mB1 = red[64 + r1s];
            float M1 = fmaxf(mA1, mB1);
            float S1 = red2[r1s] * __expf(mA1 - M1) + red2[64 + r1s] * __expf(mB1 - M1);
            float f1 = __expf(m1 - M1) / S1;
#pragma unroll
            for (int nt = 0; nt < 4; nt++) {
                int colu = swnh * 16 + nt * 4 + tid4;   // col/2
                Psm[r0s * 36 + colu] = packh2(c[nt][0] * f0, c[nt][1] * f0);
                Psm[r1s * 36 + colu] = packh2(c[nt][2] * f1, c[nt][3] * f1);
            }
        }

        // ---- V transpose STS: Vt[d][j] ----
        {
            __half2 p01 = *(__half2*)&vr0.x, p23 = *(__half2*)&vr0.y;
            int d0 = vdg0 * 4;
            Vt_h[(d0 + 0) * 72 + vj0] = p01.x;
            Vt_h[(d0 + 1) * 72 + vj0] = p01.y;
            Vt_h[(d0 + 2) * 72 + vj0] = p23.x;
            Vt_h[(d0 + 3) * 72 + vj0] = p23.y;
            if (hasu1) {
                __half2 q01 = *(__half2*)&vr1.x, q23 = *(__half2*)&vr1.y;
                int d1 = vdg1 * 4;
                Vt_h[(d1 + 0) * 72 + vj1] = q01.x;
                Vt_h[(d1 + 1) * 72 + vj1] = q01.y;
                Vt_h[(d1 + 2) * 72 + vj1] = q23.x;
                Vt_h[(d1 + 3) * 72 + vj1] = q23.y;
            }
        }
        __syncthreads();

        // ---- O = P @ V (fp16 k16) ----
        float c2[2][4];
#pragma unroll
        for (int i = 0; i < 2; i++)
#pragma unroll
            for (int j = 0; j < 4; j++) c2[i][j] = 0.f;

        const int pr0 = pwm + gid, pr1 = pr0 + 8;
#pragma unroll
        for (int ks = 0; ks < 4; ks++) {
            unsigned a[4];
            a[0] = Psm[pr0 * 36 + ks * 8 + tid4];
            a[1] = Psm[pr1 * 36 + ks * 8 + tid4];
            a[2] = Psm[pr0 * 36 + ks * 8 + tid4 + 4];
            a[3] = Psm[pr1 * 36 + ks * 8 + tid4 + 4];
#pragma unroll
            for (int nt = 0; nt < 2; nt++) {
                int d = pwn + nt * 8 + gid;
                unsigned bb[2];
                bb[0] = Vt[d * 36 + ks * 8 + tid4];
                bb[1] = Vt[d * 36 + ks * 8 + tid4 + 4];
                mma_f16(c2[nt], a, bb);
            }
        }

        // ---- write O fp16 ----
        __half* gOb = gO + h * 32;
#pragma unroll
        for (int nt = 0; nt < 2; nt++) {
            int col = pwn + nt * 8 + tid4 * 2;
            if (pr0 < 49)
                *(unsigned*)&gOb[(size_t)pr0 * 256 + col] = packh2(c2[nt][0], c2[nt][1]);
            if (pr1 < 49)
                *(unsigned*)&gOb[(size_t)pr1 * 256 + col] = packh2(c2[nt][2], c2[nt][3]);
        }
        // next head's top barrier orders PV/Psm reads before stage reuse
    }
}

// ---------------- nuclei passthrough ----------------
__global__ void copy_nuc(const float* __restrict__ in, float* __restrict__ out, int n4)
{
    int i = blockIdx.x * 256 + threadIdx.x;
    if (i < n4) ((float4*)out)[i] = ((const float4*)in)[i];
}

// ---------------- launch ----------------
extern "C" void kernel_launch(void* const* d_in, const int* in_sizes, int n_in,
                              void* d_out, int out_size)
{
    const float* x        = (const float*)d_in[0];
    const float* y        = (const float*)d_in[1];
    const float* nuc      = (const float*)d_in[2];
    const float* mask     = (const float*)d_in[3];
    const float* rpbt     = (const float*)d_in[4];
    const float* qkv_w    = (const float*)d_in[5];
    const float* qkv_b    = (const float*)d_in[6];
    const float* qkv_y_w  = (const float*)d_in[7];
    const float* qkv_y_b  = (const float*)d_in[8];
    const float* proj_qx_w= (const float*)d_in[9];
    const float* proj_qx_b= (const float*)d_in[10];
    const float* proj_qy_w= (const float*)d_in[11];
    const float* proj_qy_b= (const float*)d_in[12];
    const float* proj_w   = (const float*)d_in[13];
    const float* proj_b   = (const float*)d_in[14];
    const float* proj_y_w = (const float*)d_in[15];
    const float* proj_y_b = (const float*)d_in[16];
    const int*   rpi      = (const int*)d_in[17];
    float* out = (float*)d_out;

    __half *xbuf, *ybuf, *ox, *oy, *wx, *wy, *pw, *py;
    float *bx, *by, *rpbH;
    cudaGetSymbolAddress((void**)&xbuf, g_xbuf);
    cudaGetSymbolAddress((void**)&ybuf, g_ybuf);
    cudaGetSymbolAddress((void**)&ox,   g_ox);
    cudaGetSymbolAddress((void**)&oy,   g_oy);
    cudaGetSymbolAddress((void**)&wx,   g_wx);
    cudaGetSymbolAddress((void**)&wy,   g_wy);
    cudaGetSymbolAddress((void**)&pw,   g_pw);
    cudaGetSymbolAddress((void**)&py,   g_py);
    cudaGetSymbolAddress((void**)&bx,   g_bx);
    cudaGetSymbolAddress((void**)&by,   g_by);
    cudaGetSymbolAddress((void**)&rpbH, g_rpbH);

    cudaFuncSetAttribute(attn_kernel, cudaFuncAttributeMaxDynamicSharedMemorySize,
                         ATTN_SMEM_BYTES);
    cudaFuncSetAttribute((const void*)gemm_h<0>, cudaFuncAttributeMaxDynamicSharedMemorySize,
                         GEMM_SMEM_BYTES);
    cudaFuncSetAttribute((const void*)gemm_h<1>, cudaFuncAttributeMaxDynamicSharedMemorySize,
                         GEMM_SMEM_BYTES);

    // prep (tiny)
    prep_w<<<768, 256>>>(qkv_w,   qkv_b,   proj_qx_w, proj_qx_b, wx, bx);
    prep_w<<<768, 256>>>(qkv_y_w, qkv_y_b, proj_qy_w, proj_qy_b, wy, by);
    prep_p<<<256, 256>>>(proj_w,   pw);
    prep_p<<<256, 256>>>(proj_y_w, py);
    prep_rpb<<<(HEADS_ * 2401 + 255) / 256, 256>>>(rpbt, rpi, rpbH);

    const int mtiles = M_ROWS / 128;  // 1568

    // input projections (A fp32 -> C fp16), both streams
    gemm_h<0><<<dim3(6, mtiles, 2), 128, GEMM_SMEM_BYTES>>>(
        x, wx, bx, xbuf, y, wy, by, ybuf, 768);

    // attention (both paths)
    attn_kernel<<<dim3(B_B, 2), 256, ATTN_SMEM_BYTES>>>(nuc, mask, rpbH);

    // output projections (A fp16 -> C fp32), both
    gemm_h<1><<<dim3(2, mtiles, 2), 128, GEMM_SMEM_BYTES>>>(
        ox, pw, proj_b, out, oy, py, proj_y_b, out + (size_t)M_ROWS * 256, 256);

    copy_nuc<<<(M_ROWS / 4 + 255) / 256, 256>>>(nuc, out + 2 * (size_t)M_ROWS * 256,
                                                M_ROWS / 4);
}

// round 10
// speedup vs baseline: 5.9048x; 1.1197x over previous
#include <cuda_runtime.h>
#include <cuda_fp16.h>
#include <cstdint>

#define B_B 4096
#define HEADS_ 8
#define NW_ 64
#define Q_SCALE 0.17677669529663687f
#define M_ROWS (B_B * 49)              // 200704 = 1568 * 128

// ---------------- scratch ----------------
__device__ __align__(16) __half g_xbuf[(size_t)M_ROWS * 768];  // k|v|q fp16
__device__ __align__(16) __half g_ybuf[(size_t)M_ROWS * 768];
__device__ __align__(16) __half g_ox  [(size_t)M_ROWS * 256];
__device__ __align__(16) __half g_oy  [(size_t)M_ROWS * 256];
__device__ __align__(16) __half g_wx  [768 * 256];  // W^T [n][k] fp16
__device__ __align__(16) __half g_wy  [768 * 256];
__device__ __align__(16) __half g_pw  [256 * 256];
__device__ __align__(16) __half g_py  [256 * 256];
__device__ __align__(16) float  g_bx  [768];
__device__ __align__(16) float  g_by  [768];
__device__ __align__(16) float  g_rpbH[HEADS_ * 2452 + 64];    // +64 OOB pad

// ---------------- helpers ----------------
__device__ __forceinline__ uint32_t smem_u32(const void* p) {
    uint32_t a;
    asm("{ .reg .u64 t; cvta.to.shared.u64 t, %1; cvt.u32.u64 %0, t; }" : "=r"(a) : "l"(p));
    return a;
}
__device__ __forceinline__ unsigned packh2(float a, float b) {
    __half2 h = __floats2half2_rn(a, b);
    return *(unsigned*)&h;
}
__device__ __forceinline__ void mma_f16(float* c, const unsigned* a, const unsigned* b) {
    asm volatile(
        "mma.sync.aligned.m16n8k16.row.col.f32.f16.f16.f32 "
        "{%0,%1,%2,%3}, {%4,%5,%6,%7}, {%8,%9}, {%0,%1,%2,%3};\n"
        : "+f"(c[0]), "+f"(c[1]), "+f"(c[2]), "+f"(c[3])
        : "r"(a[0]), "r"(a[1]), "r"(a[2]), "r"(a[3]), "r"(b[0]), "r"(b[1]));
}
__device__ __forceinline__ void ldm_x4(unsigned* r, uint32_t addr) {
    asm volatile("ldmatrix.sync.aligned.m8n8.x4.shared.b16 {%0,%1,%2,%3}, [%4];"
        : "=r"(r[0]), "=r"(r[1]), "=r"(r[2]), "=r"(r[3]) : "r"(addr));
}
__device__ __forceinline__ void cpasync16(uint32_t dst, const void* src) {
    asm volatile("cp.async.cg.shared.global [%0], [%1], 16;" :: "r"(dst), "l"(src));
}
#define CP_COMMIT() asm volatile("cp.async.commit_group;" ::: "memory")

// ---------------- prep ----------------
__global__ void prep_w(const float* __restrict__ qkv_w, const float* __restrict__ qkv_b,
                       const float* __restrict__ qw, const float* __restrict__ qb,
                       __half* __restrict__ WT, float* __restrict__ bc)
{
    int i = blockIdx.x * 256 + threadIdx.x;
    if (i < 768 * 256) {
        int n = i >> 8, k = i & 255;
        float v = (n < 512) ? qkv_w[k * 512 + n] : qw[k * 256 + (n - 512)] * Q_SCALE;
        WT[i] = __float2half_rn(v);
    }
    if (i < 768) bc[i] = (i < 512) ? qkv_b[i] : qb[i - 512] * Q_SCALE;
}
__global__ void prep_p(const float* __restrict__ W, __half* __restrict__ WT)
{
    int i = blockIdx.x * 256 + threadIdx.x;
    if (i < 65536) { int n = i >> 8, k = i & 255; WT[i] = __float2half_rn(W[k * 256 + n]); }
}
__global__ void prep_rpb(const float* __restrict__ rpbt, const int* __restrict__ rpi,
                         float* __restrict__ rpbH)
{
    int i = blockIdx.x * 256 + threadIdx.x;
    if (i < HEADS_ * 2401) {
        int h = i / 2401, ij = i % 2401;
        int r = ij / 49, j = ij % 49;
        rpbH[h * 2452 + r * 50 + j] = rpbt[rpi[ij] * 8 + h];
    }
}

// ---------------- fp16 mma GEMM w/ ldmatrix, warp tile 64x64 ----------------
#define GH_AS0  0
#define GH_AS1  2560
#define GH_BS0  5120
#define GH_BS1  7680
#define GEMM_SMEM_BYTES (10240 * 4)

template<int AFP16>
__global__ __launch_bounds__(128) void gemm_h(
    const void* __restrict__ A0v, const __half* __restrict__ W0,
    const float* __restrict__ b0, void* __restrict__ C0v,
    const void* __restrict__ A1v, const __half* __restrict__ W1,
    const float* __restrict__ b1, void* __restrict__ C1v, int Ncol)
{
    extern __shared__ unsigned smg[];
    const uint32_t sb = smem_u32(smg);

    const void*  Av   = blockIdx.z ? A1v : A0v;
    const __half* W   = blockIdx.z ? W1 : W0;
    const float* bias = blockIdx.z ? b1 : b0;
    void*        Cv   = blockIdx.z ? C1v : C0v;

    const int t = threadIdx.x;
    const int warpId = t >> 5, lane = t & 31;
    const int gid = lane >> 2, tid4 = lane & 3;
    const int wm = (warpId & 1) * 64;
    const int wn = (warpId >> 1) * 64;
    const size_t tileM = (size_t)blockIdx.y * 128;
    const int tileN = blockIdx.x * 128;

    // ldmatrix lane-address components
    const int mi = lane >> 3, li = lane & 7;
    uint32_t aRel[4], bRel[4];
#pragma unroll
    for (int mt = 0; mt < 4; mt++)
        aRel[mt] = (uint32_t)(((wm + mt * 16 + (mi & 1) * 8 + li) * 20 + (mi >> 1) * 4) * 4);
#pragma unroll
    for (int np = 0; np < 4; np++)
        bRel[np] = (uint32_t)(((wn + (2 * np + (mi >> 1)) * 8 + li) * 20 + (mi & 1) * 4) * 4);

    float acc[4][8][4];
#pragma unroll
    for (int i = 0; i < 4; i++)
#pragma unroll
        for (int j = 0; j < 8; j++)
#pragma unroll
            for (int l = 0; l < 4; l++) acc[i][j][l] = 0.f;

#define GH_BFILL(stage, ch) do {                                                     \
    uint32_t bs_ = sb + ((stage) ? GH_BS1 : GH_BS0) * 4;                             \
    const __half* wsrc_ = W + (size_t)(tileN + t) * 256 + (ch) * 32;                 \
    _Pragma("unroll")                                                                \
    for (int cc = 0; cc < 4; cc++)                                                   \
        cpasync16(bs_ + (uint32_t)((t * 20 + cc * 4) * 4), wsrc_ + cc * 8);          \
} while (0)
#define GH_AFILL16(stage, ch) do {                                                   \
    uint32_t as_ = sb + ((stage) ? GH_AS1 : GH_AS0) * 4;                             \
    const __half* asrc_ = (const __half*)Av + (tileM + t) * 256 + (ch) * 32;         \
    _Pragma("unroll")                                                                \
    for (int cc = 0; cc < 4; cc++)                                                   \
        cpasync16(as_ + (uint32_t)((t * 20 + cc * 4) * 4), asrc_ + cc * 8);          \
} while (0)

    const int arow0 = t >> 3, aq = t & 7;
    const float* Af = (const float*)Av;
    float4 pa[8];

    if (AFP16) {
        GH_AFILL16(0, 0); GH_BFILL(0, 0); CP_COMMIT();
        GH_AFILL16(1, 1); GH_BFILL(1, 1); CP_COMMIT();
    } else {
#pragma unroll
        for (int i = 0; i < 8; i++)
            pa[i] = *(const float4*)(Af + (tileM + arow0 + i * 16) * 256 + aq * 4);
        GH_BFILL(0, 0); CP_COMMIT();
        GH_BFILL(1, 1); CP_COMMIT();
    }

    for (int c = 0; c < 8; c++) {
        const int s = c & 1;
        unsigned* As = smg + (s ? GH_AS1 : GH_AS0);
        const uint32_t aBase = sb + (s ? GH_AS1 : GH_AS0) * 4;
        const uint32_t bBase = sb + (s ? GH_BS1 : GH_BS0) * 4;

        if (!AFP16) {
#pragma unroll
            for (int i = 0; i < 8; i++) {
                uint2 u = { packh2(pa[i].x, pa[i].y), packh2(pa[i].z, pa[i].w) };
                *(uint2*)&As[(arow0 + i * 16) * 20 + aq * 2] = u;
            }
        }
        if (c < 7) asm volatile("cp.async.wait_group 1;" ::: "memory");
        else       asm volatile("cp.async.wait_group 0;" ::: "memory");
        __syncthreads();

        if (!AFP16 && c < 7) {
#pragma unroll
            for (int i = 0; i < 8; i++)
                pa[i] = *(const float4*)(Af + (tileM + arow0 + i * 16) * 256
                                         + (c + 1) * 32 + aq * 4);
        }

#pragma unroll
        for (int ks = 0; ks < 2; ks++) {
            unsigned a[4][4];
#pragma unroll
            for (int mt = 0; mt < 4; mt++)
                ldm_x4(a[mt], aBase + aRel[mt] + ks * 32);
            unsigned bf[4][4];
#pragma unroll
            for (int np = 0; np < 4; np++)
                ldm_x4(bf[np], bBase + bRel[np] + ks * 32);
#pragma unroll
            for (int nt = 0; nt < 8; nt++) {
                unsigned b2[2] = { bf[nt >> 1][(nt & 1) * 2], bf[nt >> 1][(nt & 1) * 2 + 1] };
#pragma unroll
                for (int mt = 0; mt < 4; mt++)
                    mma_f16(acc[mt][nt], a[mt], b2);
            }
        }
        __syncthreads();

        if (c < 6) {
            if (AFP16) GH_AFILL16(s, c + 2);
            GH_BFILL(s, c + 2);
            CP_COMMIT();
        }
    }

    // epilogue
#pragma unroll
    for (int mt = 0; mt < 4; mt++) {
        size_t row0 = tileM + wm + mt * 16 + gid;
#pragma unroll
        for (int nt = 0; nt < 8; nt++) {
            int col = tileN + wn + nt * 8 + tid4 * 2;
            float bb0 = bias[col], bb1 = bias[col + 1];
            float o0 = acc[mt][nt][0] + bb0, o1 = acc[mt][nt][1] + bb1;
            float o2 = acc[mt][nt][2] + bb0, o3 = acc[mt][nt][3] + bb1;
            if (AFP16) {
                float* C = (float*)Cv;
                float2 v0 = { o0, o1 }, v1 = { o2, o3 };
                *(float2*)&C[row0 * Ncol + col] = v0;
                *(float2*)&C[(row0 + 8) * Ncol + col] = v1;
            } else {
                __half* C = (__half*)Cv;
                *(unsigned*)&C[row0 * Ncol + col] = packh2(o0, o1);
                *(unsigned*)&C[(row0 + 8) * Ncol + col] = packh2(o2, o3);
            }
        }
    }
}

// ---------------- attention v2: warp-per-16-rows, register P ----------------
// 256 threads = 8 warps; 4 iterations x 2 heads. Warp w: head 2*it+(w>>2),
// rows (w&3)*16. smem (uints):
//   stage s: 2 heads x [Qt 64x20 | Kt 64x20] = 5120 each, stages at 0 / 5120
//   Vt: 2 head-slots x 32(d) x 36 = 2304 at 10240
//   base floats at 12544, size 2452 + 64 pad
#define AT_ST0  0
#define AT_ST1  5120
#define AT_VT   10240
#define AT_BASE 12544
#define AT_TOT  (AT_BASE + 2452 + 64)    // 15060 u
#define ATTN_SMEM_BYTES (AT_TOT * 4)     // 60,240 B

__device__ __forceinline__ void fill_qk2(uint32_t sb, int stw,
    const __half* Q, const __half* K, int h0, int t)
{
    for (int u = t; u < 784; u += 256) {
        int tz = u / 196, rem = u - tz * 196;
        int g = tz >> 1, qk = tz & 1;
        int row = rem >> 2, cc = rem & 3;
        const __half* src = (qk ? K : Q) + (size_t)(h0 + g) * 32 + row * 768 + cc * 8;
        uint32_t dstw = (uint32_t)(stw + g * 2560 + qk * 1280 + row * 20 + cc * 4);
        cpasync16(sb + dstw * 4, src);
    }
}

__global__ __launch_bounds__(256) void attn_kernel(
    const float* __restrict__ nuc, const float* __restrict__ mask,
    const float* __restrict__ rpbH)
{
    extern __shared__ unsigned smw[];
    const uint32_t sb = smem_u32(smw);
    float* base = (float*)(smw + AT_BASE);

    const int b = blockIdx.x;
    const int path = blockIdx.y;
    const __half* Q  = (path ? g_xbuf : g_ybuf) + 512 + (size_t)b * 49 * 768;
    const __half* KV = (path ? g_ybuf : g_xbuf) + (size_t)b * 49 * 768;
    __half* gO       = (path ? g_oy : g_ox) + (size_t)b * 49 * 256;

    const int t = threadIdx.x;
    const int w = t >> 5, lane = t & 31;
    const int gid = lane >> 2, tid4 = lane & 3;
    const int g = w >> 2;                 // head slot (0/1)
    const int R = (w & 3) * 16;           // row block
    const int wi = b & (NW_ - 1);
    const float* nb = nuc + (size_t)b * 49;

    const int r0 = R + gid, r1 = r0 + 8;
    const bool v0 = r0 < 49, v1 = r1 < 49;
    const int br0 = v0 ? r0 : 0, br1 = v1 ? r1 : 0;   // clamped bias rows

    // ldmatrix lane-address components
    const int mi = lane >> 3, li = lane & 7;
    const uint32_t aRel = (uint32_t)((g * 2560 + (R + (mi & 1) * 8 + li) * 20 + (mi >> 1) * 4) * 4);
    uint32_t kRel[4];
#pragma unroll
    for (int np = 0; np < 4; np++)
        kRel[np] = (uint32_t)((g * 2560 + 1280 + ((2 * np + (mi >> 1)) * 8 + li) * 20 + (mi & 1) * 4) * 4);
    uint32_t vAddr[2];
#pragma unroll
    for (int np = 0; np < 2; np++)
        vAddr[np] = sb + (uint32_t)((AT_VT + g * 1152 + ((2 * np + (mi >> 1)) * 8 + li) * 36 + (mi & 1) * 4) * 4);

    // prologue fill: heads 0,1
    fill_qk2(sb, AT_ST0, Q, KV, 0, t);
    CP_COMMIT();

    // one-time: base table + zero Vt (pads stay 0)
    for (int idx = t; idx < 2401; idx += 256) {
        int i = idx / 49, j = idx % 49;
        base[i * 50 + j] = nb[i] + nb[j] + mask[((size_t)wi * 49 + i) * 49 + j];
    }
    for (int idx = t; idx < 2304; idx += 256) smw[AT_VT + idx] = 0u;

    const int tl = t & 127;               // thread-in-group
    __half* VtH = (__half*)(smw + AT_VT) + g * 2304;

    for (int it = 0; it < 4; it++) {
        const int h = 2 * it + g;
        const int stw = (it & 1) ? AT_ST1 : AT_ST0;
        asm volatile("cp.async.wait_group 0;" ::: "memory");
        __syncthreads();

        if (it < 3) {
            fill_qk2(sb, (it & 1) ? AT_ST0 : AT_ST1, Q, KV, 2 * it + 2, t);
            CP_COMMIT();
        }

        // V LDG for this group's head (into regs; STS after softmax)
        const __half* Vb = KV + 256 + (size_t)h * 32;
        uint2 vreg[4];
#pragma unroll
        for (int i = 0; i < 4; i++) {
            int u = tl + i * 128;
            if (u < 392)
                vreg[i] = *(const uint2*)(Vb + (size_t)(u >> 3) * 768 + (u & 7) * 4);
        }

        const uint32_t stB = sb + (uint32_t)stw * 4;

        // ---- S = Q @ K^T : warp covers rows R..R+15, all 64 cols ----
        float cS[8][4];
#pragma unroll
        for (int i = 0; i < 8; i++)
#pragma unroll
            for (int j = 0; j < 4; j++) cS[i][j] = 0.f;
#pragma unroll
        for (int ks = 0; ks < 2; ks++) {
            unsigned a[4];
            ldm_x4(a, stB + aRel + ks * 32);
#pragma unroll
            for (int np = 0; np < 4; np++) {
                unsigned bf[4];
                ldm_x4(bf, stB + kRel[np] + ks * 32);
                unsigned b0[2] = { bf[0], bf[1] }, b1[2] = { bf[2], bf[3] };
                mma_f16(cS[2 * np], a, b0);
                mma_f16(cS[2 * np + 1], a, b1);
            }
        }

        // ---- bias/mask (base smem + rpb L2, float2 pairs) ----
        const float* rpb = rpbH + h * 2452;
#pragma unroll
        for (int nt = 0; nt < 8; nt++) {
            int col = nt * 8 + tid4 * 2;
            bool jc0 = col < 49, jc1 = col < 48;
            float2 bs0 = *(const float2*)&base[br0 * 50 + col];
            float2 bs1 = *(const float2*)&base[br1 * 50 + col];
            float2 rp0 = *(const float2*)&rpb[br0 * 50 + col];
            float2 rp1 = *(const float2*)&rpb[br1 * 50 + col];
            cS[nt][0] = (v0 && jc0) ? cS[nt][0] + bs0.x + rp0.x : (v0 ? -1e30f : 0.f);
            cS[nt][1] = (v0 && jc1) ? cS[nt][1] + bs0.y + rp0.y : (v0 ? -1e30f : 0.f);
            cS[nt][2] = (v1 && jc0) ? cS[nt][2] + bs1.x + rp1.x : (v1 ? -1e30f : 0.f);
            cS[nt][3] = (v1 && jc1) ? cS[nt][3] + bs1.y + rp1.y : (v1 ? -1e30f : 0.f);
        }

        // ---- softmax fully in-warp ----
        float m0 = -1e30f, m1 = -1e30f;
#pragma unroll
        for (int nt = 0; nt < 8; nt++) {
            m0 = fmaxf(m0, fmaxf(cS[nt][0], cS[nt][1]));
            m1 = fmaxf(m1, fmaxf(cS[nt][2], cS[nt][3]));
        }
#pragma unroll
        for (int o = 1; o <= 2; o <<= 1) {
            m0 = fmaxf(m0, __shfl_xor_sync(0xffffffffu, m0, o));
            m1 = fmaxf(m1, __shfl_xor_sync(0xffffffffu, m1, o));
        }
        float s0 = 0.f, s1 = 0.f;
#pragma unroll
        for (int nt = 0; nt < 8; nt++) {
            cS[nt][0] = __expf(cS[nt][0] - m0);
            cS[nt][1] = __expf(cS[nt][1] - m0);
            cS[nt][2] = __expf(cS[nt][2] - m1);
            cS[nt][3] = __expf(cS[nt][3] - m1);
            s0 += cS[nt][0] + cS[nt][1];
            s1 += cS[nt][2] + cS[nt][3];
        }
#pragma unroll
        for (int o = 1; o <= 2; o <<= 1) {
            s0 += __shfl_xor_sync(0xffffffffu, s0, o);
            s1 += __shfl_xor_sync(0xffffffffu, s1, o);
        }
        const float f0 = 1.f / s0, f1 = 1.f / s1;

        // ---- P: register repack to PV a-frags (fp16) ----
        unsigned pA[4][4];
#pragma unroll
        for (int ks = 0; ks < 4; ks++) {
            pA[ks][0] = packh2(cS[2 * ks][0] * f0,     cS[2 * ks][1] * f0);
            pA[ks][1] = packh2(cS[2 * ks][2] * f1,     cS[2 * ks][3] * f1);
            pA[ks][2] = packh2(cS[2 * ks + 1][0] * f0, cS[2 * ks + 1][1] * f0);
            pA[ks][3] = packh2(cS[2 * ks + 1][2] * f1, cS[2 * ks + 1][3] * f1);
        }

        // ---- V transpose STS (group-local) ----
#pragma unroll
        for (int i = 0; i < 4; i++) {
            int u = tl + i * 128;
            if (u < 392) {
                int j = u >> 3, d0 = (u & 7) * 4;
                __half2 p01 = *(__half2*)&vreg[i].x, p23 = *(__half2*)&vreg[i].y;
                VtH[(d0 + 0) * 72 + j] = p01.x;
                VtH[(d0 + 1) * 72 + j] = p01.y;
                VtH[(d0 + 2) * 72 + j] = p23.x;
                VtH[(d0 + 3) * 72 + j] = p23.y;
            }
        }
        asm volatile("bar.sync %0, %1;" :: "r"(g + 1), "r"(128) : "memory");

        // ---- O = P @ V ----
        float c2[4][4];
#pragma unroll
        for (int i = 0; i < 4; i++)
#pragma unroll
            for (int j = 0; j < 4; j++) c2[i][j] = 0.f;
#pragma unroll
        for (int ks = 0; ks < 4; ks++) {
#pragma unroll
            for (int np = 0; np < 2; np++) {
                unsigned bf[4];
                ldm_x4(bf, vAddr[np] + ks * 32);
                unsigned b0[2] = { bf[0], bf[1] }, b1[2] = { bf[2], bf[3] };
                mma_f16(c2[2 * np], pA[ks], b0);
                mma_f16(c2[2 * np + 1], pA[ks], b1);
            }
        }

        // ---- O store fp16 ----
        __half* gOb = gO + h * 32;
#pragma unroll
        for (int nt = 0; nt < 4; nt++) {
            int col = nt * 8 + tid4 * 2;
            if (v0) *(unsigned*)&gOb[(size_t)r0 * 256 + col] = packh2(c2[nt][0], c2[nt][1]);
            if (v1) *(unsigned*)&gOb[(size_t)r1 * 256 + col] = packh2(c2[nt][2], c2[nt][3]);
        }
    }
}

// ---------------- nuclei passthrough ----------------
__global__ void copy_nuc(const float* __restrict__ in, float* __restrict__ out, int n4)
{
    int i = blockIdx.x * 256 + threadIdx.x;
    if (i < n4) ((float4*)out)[i] = ((const float4*)in)[i];
}

// ---------------- launch ----------------
extern "C" void kernel_launch(void* const* d_in, const int* in_sizes, int n_in,
                              void* d_out, int out_size)
{
    const float* x        = (const float*)d_in[0];
    const float* y        = (const float*)d_in[1];
    const float* nuc      = (const float*)d_in[2];
    const float* mask     = (const float*)d_in[3];
    const float* rpbt     = (const float*)d_in[4];
    const float* qkv_w    = (const float*)d_in[5];
    const float* qkv_b    = (const float*)d_in[6];
    const float* qkv_y_w  = (const float*)d_in[7];
    const float* qkv_y_b  = (const float*)d_in[8];
    const float* proj_qx_w= (const float*)d_in[9];
    const float* proj_qx_b= (const float*)d_in[10];
    const float* proj_qy_w= (const float*)d_in[11];
    const float* proj_qy_b= (const float*)d_in[12];
    const float* proj_w   = (const float*)d_in[13];
    const float* proj_b   = (const float*)d_in[14];
    const float* proj_y_w = (const float*)d_in[15];
    const float* proj_y_b = (const float*)d_in[16];
    const int*   rpi      = (const int*)d_in[17];
    float* out = (float*)d_out;

    __half *xbuf, *ybuf, *ox, *oy, *wx, *wy, *pw, *py;
    float *bx, *by, *rpbH;
    cudaGetSymbolAddress((void**)&xbuf, g_xbuf);
    cudaGetSymbolAddress((void**)&ybuf, g_ybuf);
    cudaGetSymbolAddress((void**)&ox,   g_ox);
    cudaGetSymbolAddress((void**)&oy,   g_oy);
    cudaGetSymbolAddress((void**)&wx,   g_wx);
    cudaGetSymbolAddress((void**)&wy,   g_wy);
    cudaGetSymbolAddress((void**)&pw,   g_pw);
    cudaGetSymbolAddress((void**)&py,   g_py);
    cudaGetSymbolAddress((void**)&bx,   g_bx);
    cudaGetSymbolAddress((void**)&by,   g_by);
    cudaGetSymbolAddress((void**)&rpbH, g_rpbH);

    cudaFuncSetAttribute(attn_kernel, cudaFuncAttributeMaxDynamicSharedMemorySize,
                         ATTN_SMEM_BYTES);
    cudaFuncSetAttribute((const void*)gemm_h<0>, cudaFuncAttributeMaxDynamicSharedMemorySize,
                         GEMM_SMEM_BYTES);
    cudaFuncSetAttribute((const void*)gemm_h<1>, cudaFuncAttributeMaxDynamicSharedMemorySize,
                         GEMM_SMEM_BYTES);

    // prep (tiny)
    prep_w<<<768, 256>>>(qkv_w,   qkv_b,   proj_qx_w, proj_qx_b, wx, bx);
    prep_w<<<768, 256>>>(qkv_y_w, qkv_y_b, proj_qy_w, proj_qy_b, wy, by);
    prep_p<<<256, 256>>>(proj_w,   pw);
    prep_p<<<256, 256>>>(proj_y_w, py);
    prep_rpb<<<(HEADS_ * 2401 + 255) / 256, 256>>>(rpbt, rpi, rpbH);

    const int mtiles = M_ROWS / 128;  // 1568

    // input projections (A fp32 -> C fp16), both streams
    gemm_h<0><<<dim3(6, mtiles, 2), 128, GEMM_SMEM_BYTES>>>(
        x, wx, bx, xbuf, y, wy, by, ybuf, 768);

    // attention (both paths)
    attn_kernel<<<dim3(B_B, 2), 256, ATTN_SMEM_BYTES>>>(nuc, mask, rpbH);

    // output projections (A fp16 -> C fp32), both
    gemm_h<1><<<dim3(2, mtiles, 2), 128, GEMM_SMEM_BYTES>>>(
        ox, pw, proj_b, out, oy, py, proj_y_b, out + (size_t)M_ROWS * 256, 256);

    copy_nuc<<<(M_ROWS / 4 + 255) / 256, 256>>>(nuc, out + 2 * (size_t)M_ROWS * 256,
                                                M_ROWS / 4);
}